// round 7
// baseline (speedup 1.0000x reference)
#include <cuda_runtime.h>
#include <math.h>

#define B_    4
#define S_    2048
#define DE    1024
#define NH    16
#define DH    64
#define BSROWS (B_ * S_)   // 8192

// Scratch (allocation-free per harness rules; __device__ globals)
__device__ float g_qp[(size_t)BSROWS * DE];
__device__ float g_kp[(size_t)BSROWS * DE];
__device__ float g_vp[(size_t)BSROWS * DE];
__device__ float g_at[(size_t)BSROWS * DE];
__device__ float2 g_rope[(size_t)S_ * 32];   // (cos, sin) per (position, pair)

// ---------------------------------------------------------------------------
// C[M][N] = A[M][K] @ B[N][K]^T   (both row-major, K contiguous)
// ---------------------------------------------------------------------------
#define BM 128
#define BN 64
#define BK 16
#define PADA 132
#define PADB 68

__global__ __launch_bounds__(256) void gemm_nt(const float* __restrict__ A,
                                               const float* __restrict__ B,
                                               float* __restrict__ C,
                                               int M, int N, int K) {
    __shared__ float As[BK][PADA];
    __shared__ float Bs[BK][PADB];

    const int tid = threadIdx.x;
    const int ty = tid >> 4;
    const int tx = tid & 15;
    const int bm = blockIdx.y * BM;
    const int bn = blockIdx.x * BN;

    float acc[8][4];
#pragma unroll
    for (int i = 0; i < 8; i++)
#pragma unroll
        for (int j = 0; j < 4; j++) acc[i][j] = 0.f;

    for (int k0 = 0; k0 < K; k0 += BK) {
#pragma unroll
        for (int p = 0; p < 2; p++) {
            int idx = tid + p * 256;
            int r = idx >> 2;
            int kq = (idx & 3) << 2;
            float4 v = *(const float4*)&A[(size_t)(bm + r) * K + k0 + kq];
            As[kq + 0][r] = v.x;
            As[kq + 1][r] = v.y;
            As[kq + 2][r] = v.z;
            As[kq + 3][r] = v.w;
        }
        {
            int r = tid >> 2;
            int kq = (tid & 3) << 2;
            float4 v = *(const float4*)&B[(size_t)(bn + r) * K + k0 + kq];
            Bs[kq + 0][r] = v.x;
            Bs[kq + 1][r] = v.y;
            Bs[kq + 2][r] = v.z;
            Bs[kq + 3][r] = v.w;
        }
        __syncthreads();

#pragma unroll
        for (int kk = 0; kk < BK; kk++) {
            float4 a0 = *(const float4*)&As[kk][ty * 8];
            float4 a1 = *(const float4*)&As[kk][ty * 8 + 4];
            float4 b0 = *(const float4*)&Bs[kk][tx * 4];
            float ra[8] = {a0.x, a0.y, a0.z, a0.w, a1.x, a1.y, a1.z, a1.w};
            float rb[4] = {b0.x, b0.y, b0.z, b0.w};
#pragma unroll
            for (int i = 0; i < 8; i++)
#pragma unroll
                for (int j = 0; j < 4; j++)
                    acc[i][j] = fmaf(ra[i], rb[j], acc[i][j]);
        }
        __syncthreads();
    }

#pragma unroll
    for (int i = 0; i < 8; i++) {
        float4 o = {acc[i][0], acc[i][1], acc[i][2], acc[i][3]};
        *(float4*)&C[(size_t)(bm + ty * 8 + i) * N + bn + tx * 4] = o;
    }
}

// ---------------------------------------------------------------------------
// RoPE table (double precision). NOTE: CUDA sincos signature is
// sincos(x, SIN_ptr, COS_ptr) — sin comes FIRST. This was the bug.
// ---------------------------------------------------------------------------
__global__ void rope_table_kernel(float2* __restrict__ t) {
    int i = blockIdx.x * blockDim.x + threadIdx.x;   // < S_*32
    int p = i & 31;
    int s = i >> 5;
    double inv = exp(-(double)p * (log(10000.0) / 32.0));
    double a = (double)s * inv;
    double sd, cd;
    sincos(a, &sd, &cd);                 // sin first, cos second (FIXED)
    t[i] = make_float2((float)cd, (float)sd);   // store (cos, sin)
}

// ---------------------------------------------------------------------------
// Causal flash attention with fused STANDARD interleaved RoPE on Q/K loads:
//   o_even = x1*cos - x2*sin ; o_odd = x1*sin + x2*cos
// Block = 8 warps, 64 q rows of one (b,h); 32-key tiles, one key per lane.
// ---------------------------------------------------------------------------
__global__ __launch_bounds__(256) void attn3_kernel(const float* __restrict__ qp,
                                                    const float* __restrict__ kp,
                                                    const float* __restrict__ vp,
                                                    const float2* __restrict__ rope_t,
                                                    float* __restrict__ outp) {
    __shared__ float Qs[64 * 65];
    __shared__ float Ks[32 * 65];
    __shared__ float Vs[32 * 65];

    const int tid = threadIdx.x;
    const int w = tid >> 5;
    const int lane = tid & 31;
    const int b = blockIdx.z, h = blockIdx.y;
    const int q0 = blockIdx.x * 64;

    const float* Qg = qp + (size_t)b * S_ * DE + h * DH;
    const float* Kg = kp + (size_t)b * S_ * DE + h * DH;
    const float* Vg = vp + (size_t)b * S_ * DE + h * DH;

    for (int idx = tid; idx < 64 * 32; idx += 256) {
        int r = idx >> 5;
        int p = idx & 31;
        float2 x = *(const float2*)&Qg[(size_t)(q0 + r) * DE + 2 * p];
        float2 cs = rope_t[(q0 + r) * 32 + p];
        Qs[r * 65 + 2 * p]     = x.x * cs.x - x.y * cs.y;
        Qs[r * 65 + 2 * p + 1] = x.x * cs.y + x.y * cs.x;
    }

    float m[8], l[8], O0[8], O1[8];
#pragma unroll
    for (int r = 0; r < 8; r++) {
        m[r] = -1e30f;
        l[r] = 0.f;
        O0[r] = 0.f;
        O1[r] = 0.f;
    }

    const int nkt = 2 * blockIdx.x + 2;
    for (int kt = 0; kt < nkt; kt++) {
        const int k0 = kt * 32;
        __syncthreads();
        for (int idx = tid; idx < 32 * 32; idx += 256) {
            int r = idx >> 5;
            int p = idx & 31;
            float2 x = *(const float2*)&Kg[(size_t)(k0 + r) * DE + 2 * p];
            float2 cs = rope_t[(k0 + r) * 32 + p];
            Ks[r * 65 + 2 * p]     = x.x * cs.x - x.y * cs.y;
            Ks[r * 65 + 2 * p + 1] = x.x * cs.y + x.y * cs.x;
            float2 u = *(const float2*)&Vg[(size_t)(k0 + r) * DE + 2 * p];
            Vs[r * 65 + 2 * p]     = u.x;
            Vs[r * 65 + 2 * p + 1] = u.y;
        }
        __syncthreads();

#pragma unroll
        for (int r = 0; r < 8; r++) {
            const int qrow = q0 + w * 8 + r;

            float s = 0.f;
#pragma unroll
            for (int d = 0; d < 64; d++)
                s = fmaf(Qs[(w * 8 + r) * 65 + d], Ks[lane * 65 + d], s);
            s *= 0.03125f;                     // 1/sqrt(1024)
            if (k0 + lane > qrow) s = -1e30f;  // causal

            float mt = s;
#pragma unroll
            for (int off = 16; off > 0; off >>= 1)
                mt = fmaxf(mt, __shfl_xor_sync(0xffffffffu, mt, off));

            float mn = fmaxf(m[r], mt);
            float alpha = expf(m[r] - mn);
            float p = expf(s - mn);

            float lt = p;
#pragma unroll
            for (int off = 16; off > 0; off >>= 1)
                lt += __shfl_xor_sync(0xffffffffu, lt, off);

            m[r] = mn;
            l[r] = l[r] * alpha + lt;
            O0[r] *= alpha;
            O1[r] *= alpha;

#pragma unroll
            for (int j = 0; j < 32; j++) {
                float pj = __shfl_sync(0xffffffffu, p, j);
                O0[r] = fmaf(pj, Vs[j * 65 + lane], O0[r]);
                O1[r] = fmaf(pj, Vs[j * 65 + 32 + lane], O1[r]);
            }
        }
    }

#pragma unroll
    for (int r = 0; r < 8; r++) {
        float inv = 1.0f / l[r];
        size_t row = (size_t)b * S_ + q0 + w * 8 + r;
        outp[row * DE + h * DH + lane] = O0[r] * inv;
        outp[row * DE + h * DH + 32 + lane] = O1[r] * inv;
    }
}

// ---------------------------------------------------------------------------
extern "C" void kernel_launch(void* const* d_in, const int* in_sizes, int n_in,
                              void* d_out, int out_size) {
    // Mapping (confirmed rounds 4-5): [0]=q [1]=k [2]=v [3]=W_q [4]=W_k
    // [5]=W_v [6]=W_o
    const float* q  = (const float*)d_in[0];
    const float* k  = (const float*)d_in[1];
    const float* v  = (const float*)d_in[2];
    const float* Wq = (const float*)d_in[3];
    const float* Wk = (const float*)d_in[4];
    const float* Wv = (const float*)d_in[5];
    const float* Wo = (const float*)d_in[6];
    float* out = (float*)d_out;

    float *qp, *kp, *vp, *at;
    float2* rope_t;
    cudaGetSymbolAddress((void**)&qp, g_qp);
    cudaGetSymbolAddress((void**)&kp, g_kp);
    cudaGetSymbolAddress((void**)&vp, g_vp);
    cudaGetSymbolAddress((void**)&at, g_at);
    cudaGetSymbolAddress((void**)&rope_t, g_rope);

    dim3 gproj(DE / BN, BSROWS / BM);   // (16, 64)

    rope_table_kernel<<<(S_ * 32) / 256, 256>>>(rope_t);

    gemm_nt<<<gproj, 256>>>(q, Wq, qp, BSROWS, DE, 2 * DE);
    gemm_nt<<<gproj, 256>>>(k, Wk, kp, BSROWS, DE, 2 * DE);
    gemm_nt<<<gproj, 256>>>(v, Wv, vp, BSROWS, DE, DE);

    attn3_kernel<<<dim3(S_ / 64, NH, B_), 256>>>(qp, kp, vp, rope_t, at);

    gemm_nt<<<gproj, 256>>>(at, Wo, out, BSROWS, DE, DE);
}

// round 9
// speedup vs baseline: 1.3334x; 1.3334x over previous
#include <cuda_runtime.h>
#include <cuda_bf16.h>
#include <math.h>
#include <stdint.h>

#define B_    4
#define S_    2048
#define DE    1024
#define NH    16
#define DH    64
#define BSROWS (B_ * S_)   // 8192

// Scratch (allocation-free per harness rules; __device__ globals)
__device__ float g_qp[(size_t)BSROWS * DE];
__device__ float g_kp[(size_t)BSROWS * DE];
__device__ float g_vp[(size_t)BSROWS * DE];
__device__ float g_at[(size_t)BSROWS * DE];
__device__ float2 g_rope[(size_t)S_ * 32];

// ===========================================================================
// Helpers
// ===========================================================================
__device__ __forceinline__ uint32_t smem_u32(const void* p) {
    uint32_t a;
    asm("{ .reg .u64 t; cvta.to.shared.u64 t, %1; cvt.u32.u64 %0, t; }"
        : "=r"(a) : "l"(p));
    return a;
}
__device__ __forceinline__ void ldm4(uint32_t* r, uint32_t addr) {
    asm volatile("ldmatrix.sync.aligned.m8n8.x4.shared.b16 {%0,%1,%2,%3}, [%4];"
                 : "=r"(r[0]), "=r"(r[1]), "=r"(r[2]), "=r"(r[3]) : "r"(addr));
}
__device__ __forceinline__ void mma16816(float* d, const uint32_t* a, const uint32_t* b) {
    asm volatile(
        "mma.sync.aligned.m16n8k16.row.col.f32.bf16.bf16.f32 "
        "{%0,%1,%2,%3}, {%4,%5,%6,%7}, {%8,%9}, {%0,%1,%2,%3};"
        : "+f"(d[0]), "+f"(d[1]), "+f"(d[2]), "+f"(d[3])
        : "r"(a[0]), "r"(a[1]), "r"(a[2]), "r"(a[3]), "r"(b[0]), "r"(b[1]));
}
__device__ __forceinline__ uint32_t pk_bf2(float a, float b) {
    __nv_bfloat162 t = __floats2bfloat162_rn(a, b);
    return *reinterpret_cast<uint32_t*>(&t);
}

// ===========================================================================
// Split-bf16 tensor-core GEMM via mma.sync (baseline PTX, works on sm_103):
//   C[M][N] = A[M][K] @ B[N][K]^T, fp32 in/out, fp32 accum.
//   x = hi + lo (bf16 each); C = hi*hi + hi*lo + lo*hi (lo*lo ~ 4e-6, dropped)
// Tile 128x128x32, 8 warps as 4(M) x 2(N); each warp 32x64 = 2 x 8 frags.
// ===========================================================================
#define PITCH 40   // bf16 elements per smem row (80B: conflict-free ldmatrix)

__global__ __launch_bounds__(256) void gemm_mma(const float* __restrict__ A,
                                                const float* __restrict__ B,
                                                float* __restrict__ C,
                                                int M, int N, int K) {
    __shared__ __nv_bfloat16 Ah[128 * PITCH], Al[128 * PITCH];
    __shared__ __nv_bfloat16 Bh[128 * PITCH], Bl[128 * PITCH];

    const int tid = threadIdx.x;
    const int wid = tid >> 5;
    const int lane = tid & 31;
    const int bm = blockIdx.y * 128;
    const int bn = blockIdx.x * 128;
    const int wm = (wid >> 1) * 32;   // warp M offset in tile
    const int wn = (wid & 1) * 64;    // warp N offset in tile

    const uint32_t sAh = smem_u32(Ah), sAl = smem_u32(Al);
    const uint32_t sBh = smem_u32(Bh), sBl = smem_u32(Bl);

    float acc[2][8][4];
#pragma unroll
    for (int f = 0; f < 2; f++)
#pragma unroll
        for (int n = 0; n < 8; n++)
#pragma unroll
            for (int i = 0; i < 4; i++) acc[f][n][i] = 0.f;

    // staging: thread owns row tid>>1, k-halfchunk (tid&1)*16
    const int row = tid >> 1;
    const int kseg = (tid & 1) * 16;
    const float* Ap = A + (size_t)(bm + row) * K + kseg;
    const float* Bp = B + (size_t)(bn + row) * K + kseg;
    const int nch = K / 32;

    float4 ar[4], br[4];
#pragma unroll
    for (int q = 0; q < 4; q++) {
        ar[q] = *(const float4*)(Ap + q * 4);
        br[q] = *(const float4*)(Bp + q * 4);
    }

    // ldmatrix per-lane addresses (element offsets; recomputed with ks below)
    const int a_row = (lane & 15);            // + wm + f*16
    const int a_k8  = (lane >> 4) << 3;       // 0 or 8
    const int b_row = (lane & 7) + ((lane & 16) ? 8 : 0);   // + wn + g*16
    const int b_k8  = (lane & 8) ? 8 : 0;

    for (int c = 0; c < nch; c++) {
        // convert + store to smem (hi/lo), 4 bf16 (8B) per float4
        const uint32_t so = (uint32_t)row * PITCH + (uint32_t)kseg;
#pragma unroll
        for (int q = 0; q < 4; q++) {
            float x0 = ar[q].x, x1 = ar[q].y, x2 = ar[q].z, x3 = ar[q].w;
            float h0 = __bfloat162float(__float2bfloat16_rn(x0));
            float h1 = __bfloat162float(__float2bfloat16_rn(x1));
            float h2 = __bfloat162float(__float2bfloat16_rn(x2));
            float h3 = __bfloat162float(__float2bfloat16_rn(x3));
            *(uint2*)&Ah[so + q * 4] = make_uint2(pk_bf2(h0, h1), pk_bf2(h2, h3));
            *(uint2*)&Al[so + q * 4] =
                make_uint2(pk_bf2(x0 - h0, x1 - h1), pk_bf2(x2 - h2, x3 - h3));

            float y0 = br[q].x, y1 = br[q].y, y2 = br[q].z, y3 = br[q].w;
            float g0 = __bfloat162float(__float2bfloat16_rn(y0));
            float g1 = __bfloat162float(__float2bfloat16_rn(y1));
            float g2 = __bfloat162float(__float2bfloat16_rn(y2));
            float g3 = __bfloat162float(__float2bfloat16_rn(y3));
            *(uint2*)&Bh[so + q * 4] = make_uint2(pk_bf2(g0, g1), pk_bf2(g2, g3));
            *(uint2*)&Bl[so + q * 4] =
                make_uint2(pk_bf2(y0 - g0, y1 - g1), pk_bf2(y2 - g2, y3 - g3));
        }
        __syncthreads();

        // prefetch next chunk (overlaps MMA work below)
        if (c + 1 < nch) {
            const float* An = Ap + (size_t)(c + 1) * 32;
            const float* Bn = Bp + (size_t)(c + 1) * 32;
#pragma unroll
            for (int q = 0; q < 4; q++) {
                ar[q] = *(const float4*)(An + q * 4);
                br[q] = *(const float4*)(Bn + q * 4);
            }
        }

#pragma unroll
        for (int ks = 0; ks < 32; ks += 16) {
            uint32_t ah[2][4], al[2][4];
#pragma unroll
            for (int f = 0; f < 2; f++) {
                uint32_t eo = ((uint32_t)(wm + f * 16 + a_row) * PITCH +
                               (uint32_t)(ks + a_k8)) * 2;
                ldm4(ah[f], sAh + eo);
                ldm4(al[f], sAl + eo);
            }
            uint32_t bh[8][2], bl[8][2];
#pragma unroll
            for (int g = 0; g < 4; g++) {
                uint32_t eo = ((uint32_t)(wn + g * 16 + b_row) * PITCH +
                               (uint32_t)(ks + b_k8)) * 2;
                uint32_t t[4];
                ldm4(t, sBh + eo);
                bh[2 * g][0] = t[0]; bh[2 * g][1] = t[1];
                bh[2 * g + 1][0] = t[2]; bh[2 * g + 1][1] = t[3];
                ldm4(t, sBl + eo);
                bl[2 * g][0] = t[0]; bl[2 * g][1] = t[1];
                bl[2 * g + 1][0] = t[2]; bl[2 * g + 1][1] = t[3];
            }
#pragma unroll
            for (int f = 0; f < 2; f++)
#pragma unroll
                for (int n = 0; n < 8; n++) {
                    mma16816(acc[f][n], ah[f], bh[n]);
                    mma16816(acc[f][n], ah[f], bl[n]);
                    mma16816(acc[f][n], al[f], bh[n]);
                }
        }
        __syncthreads();
    }

    // epilogue: direct fp32 stores (c0,c1 at row, c2,c3 at row+8)
    const int erow = lane >> 2;
    const int ecol = (lane & 3) * 2;
#pragma unroll
    for (int f = 0; f < 2; f++) {
        const size_t r0 = (size_t)(bm + wm + f * 16 + erow);
#pragma unroll
        for (int n = 0; n < 8; n++) {
            const size_t cc = (size_t)(bn + wn + n * 8 + ecol);
            *(float2*)&C[r0 * N + cc] = make_float2(acc[f][n][0], acc[f][n][1]);
            *(float2*)&C[(r0 + 8) * N + cc] = make_float2(acc[f][n][2], acc[f][n][3]);
        }
    }
}

// ===========================================================================
// RoPE table (double precision). sincos(x, SIN, COS) — sin first!
// ===========================================================================
__global__ void rope_table_kernel(float2* __restrict__ t) {
    int i = blockIdx.x * blockDim.x + threadIdx.x;
    int p = i & 31;
    int s = i >> 5;
    double inv = exp(-(double)p * (log(10000.0) / 32.0));
    double a = (double)s * inv;
    double sd, cd;
    sincos(a, &sd, &cd);
    t[i] = make_float2((float)cd, (float)sd);
}

// ===========================================================================
// Causal flash attention with fused standard interleaved RoPE (round-7, PASS)
// ===========================================================================
__global__ __launch_bounds__(256) void attn3_kernel(const float* __restrict__ qp,
                                                    const float* __restrict__ kp,
                                                    const float* __restrict__ vp,
                                                    const float2* __restrict__ rope_t,
                                                    float* __restrict__ outp) {
    __shared__ float Qs[64 * 65];
    __shared__ float Ks[32 * 65];
    __shared__ float Vs[32 * 65];

    const int tid = threadIdx.x;
    const int w = tid >> 5;
    const int lane = tid & 31;
    const int b = blockIdx.z, h = blockIdx.y;
    const int q0 = blockIdx.x * 64;

    const float* Qg = qp + (size_t)b * S_ * DE + h * DH;
    const float* Kg = kp + (size_t)b * S_ * DE + h * DH;
    const float* Vg = vp + (size_t)b * S_ * DE + h * DH;

    for (int idx = tid; idx < 64 * 32; idx += 256) {
        int r = idx >> 5;
        int p = idx & 31;
        float2 x = *(const float2*)&Qg[(size_t)(q0 + r) * DE + 2 * p];
        float2 cs = rope_t[(q0 + r) * 32 + p];
        Qs[r * 65 + 2 * p]     = x.x * cs.x - x.y * cs.y;
        Qs[r * 65 + 2 * p + 1] = x.x * cs.y + x.y * cs.x;
    }

    float m[8], l[8], O0[8], O1[8];
#pragma unroll
    for (int r = 0; r < 8; r++) {
        m[r] = -1e30f; l[r] = 0.f; O0[r] = 0.f; O1[r] = 0.f;
    }

    const int nkt = 2 * blockIdx.x + 2;
    for (int kt = 0; kt < nkt; kt++) {
        const int k0 = kt * 32;
        __syncthreads();
        for (int idx = tid; idx < 32 * 32; idx += 256) {
            int r = idx >> 5;
            int p = idx & 31;
            float2 x = *(const float2*)&Kg[(size_t)(k0 + r) * DE + 2 * p];
            float2 cs = rope_t[(k0 + r) * 32 + p];
            Ks[r * 65 + 2 * p]     = x.x * cs.x - x.y * cs.y;
            Ks[r * 65 + 2 * p + 1] = x.x * cs.y + x.y * cs.x;
            float2 u = *(const float2*)&Vg[(size_t)(k0 + r) * DE + 2 * p];
            Vs[r * 65 + 2 * p]     = u.x;
            Vs[r * 65 + 2 * p + 1] = u.y;
        }
        __syncthreads();

#pragma unroll
        for (int r = 0; r < 8; r++) {
            const int qrow = q0 + w * 8 + r;
            float s = 0.f;
#pragma unroll
            for (int d = 0; d < 64; d++)
                s = fmaf(Qs[(w * 8 + r) * 65 + d], Ks[lane * 65 + d], s);
            s *= 0.03125f;
            if (k0 + lane > qrow) s = -1e30f;

            float mt = s;
#pragma unroll
            for (int off = 16; off > 0; off >>= 1)
                mt = fmaxf(mt, __shfl_xor_sync(0xffffffffu, mt, off));

            float mn = fmaxf(m[r], mt);
            float alpha = expf(m[r] - mn);
            float p = expf(s - mn);

            float lt = p;
#pragma unroll
            for (int off = 16; off > 0; off >>= 1)
                lt += __shfl_xor_sync(0xffffffffu, lt, off);

            m[r] = mn;
            l[r] = l[r] * alpha + lt;
            O0[r] *= alpha;
            O1[r] *= alpha;

#pragma unroll
            for (int j = 0; j < 32; j++) {
                float pj = __shfl_sync(0xffffffffu, p, j);
                O0[r] = fmaf(pj, Vs[j * 65 + lane], O0[r]);
                O1[r] = fmaf(pj, Vs[j * 65 + 32 + lane], O1[r]);
            }
        }
    }

#pragma unroll
    for (int r = 0; r < 8; r++) {
        float inv = 1.0f / l[r];
        size_t row = (size_t)b * S_ + q0 + w * 8 + r;
        outp[row * DE + h * DH + lane] = O0[r] * inv;
        outp[row * DE + h * DH + 32 + lane] = O1[r] * inv;
    }
}

// ===========================================================================
extern "C" void kernel_launch(void* const* d_in, const int* in_sizes, int n_in,
                              void* d_out, int out_size) {
    const float* q  = (const float*)d_in[0];
    const float* k  = (const float*)d_in[1];
    const float* v  = (const float*)d_in[2];
    const float* Wq = (const float*)d_in[3];
    const float* Wk = (const float*)d_in[4];
    const float* Wv = (const float*)d_in[5];
    const float* Wo = (const float*)d_in[6];
    float* out = (float*)d_out;

    float *qp, *kp, *vp, *at;
    float2* rope_t;
    cudaGetSymbolAddress((void**)&qp, g_qp);
    cudaGetSymbolAddress((void**)&kp, g_kp);
    cudaGetSymbolAddress((void**)&vp, g_vp);
    cudaGetSymbolAddress((void**)&at, g_at);
    cudaGetSymbolAddress((void**)&rope_t, g_rope);

    rope_table_kernel<<<(S_ * 32) / 256, 256>>>(rope_t);

    dim3 gq(DE / 128, BSROWS / 128);  // (8, 64)
    gemm_mma<<<gq, 256>>>(q, Wq, qp, BSROWS, DE, 2 * DE);
    gemm_mma<<<gq, 256>>>(k, Wk, kp, BSROWS, DE, 2 * DE);
    gemm_mma<<<gq, 256>>>(v, Wv, vp, BSROWS, DE, DE);

    attn3_kernel<<<dim3(S_ / 64, NH, B_), 256>>>(qp, kp, vp, rope_t, at);

    gemm_mma<<<gq, 256>>>(at, Wo, out, BSROWS, DE, DE);
}

// round 10
// speedup vs baseline: 2.9103x; 2.1825x over previous
#include <cuda_runtime.h>
#include <cuda_bf16.h>
#include <math.h>
#include <stdint.h>

#define B_    4
#define S_    2048
#define DE    1024
#define NH    16
#define DH    64
#define BSROWS (B_ * S_)   // 8192

// fp32 scratch
__device__ float g_qp[(size_t)BSROWS * DE];
__device__ float g_kp[(size_t)BSROWS * DE];
__device__ float g_vp[(size_t)BSROWS * DE];
__device__ float g_at[(size_t)BSROWS * DE];
__device__ float2 g_rope[(size_t)S_ * 32];
// split-bf16 attention operands (hi/lo); vt is [b][h][d][s]
__device__ __nv_bfloat16 g_qh[(size_t)BSROWS * DE];
__device__ __nv_bfloat16 g_ql[(size_t)BSROWS * DE];
__device__ __nv_bfloat16 g_kh[(size_t)BSROWS * DE];
__device__ __nv_bfloat16 g_kl[(size_t)BSROWS * DE];
__device__ __nv_bfloat16 g_vth[(size_t)BSROWS * DE];
__device__ __nv_bfloat16 g_vtl[(size_t)BSROWS * DE];

// ===========================================================================
// Helpers
// ===========================================================================
__device__ __forceinline__ uint32_t smem_u32(const void* p) {
    uint32_t a;
    asm("{ .reg .u64 t; cvta.to.shared.u64 t, %1; cvt.u32.u64 %0, t; }"
        : "=r"(a) : "l"(p));
    return a;
}
__device__ __forceinline__ void ldm4(uint32_t* r, uint32_t addr) {
    asm volatile("ldmatrix.sync.aligned.m8n8.x4.shared.b16 {%0,%1,%2,%3}, [%4];"
                 : "=r"(r[0]), "=r"(r[1]), "=r"(r[2]), "=r"(r[3]) : "r"(addr));
}
__device__ __forceinline__ void mma16816(float* d, const uint32_t* a, const uint32_t* b) {
    asm volatile(
        "mma.sync.aligned.m16n8k16.row.col.f32.bf16.bf16.f32 "
        "{%0,%1,%2,%3}, {%4,%5,%6,%7}, {%8,%9}, {%0,%1,%2,%3};"
        : "+f"(d[0]), "+f"(d[1]), "+f"(d[2]), "+f"(d[3])
        : "r"(a[0]), "r"(a[1]), "r"(a[2]), "r"(a[3]), "r"(b[0]), "r"(b[1]));
}
__device__ __forceinline__ uint32_t pk_bf2(float a, float b) {
    __nv_bfloat162 t = __floats2bfloat162_rn(a, b);
    return *reinterpret_cast<uint32_t*>(&t);
}
__device__ __forceinline__ void split2(float a, float b, uint32_t& hi, uint32_t& lo) {
    float ha = __bfloat162float(__float2bfloat16_rn(a));
    float hb = __bfloat162float(__float2bfloat16_rn(b));
    hi = pk_bf2(ha, hb);
    lo = pk_bf2(a - ha, b - hb);
}

// ===========================================================================
// Split-bf16 tensor-core GEMM (round-9, PASS — unchanged)
// ===========================================================================
#define PITCH 40

__global__ __launch_bounds__(256) void gemm_mma(const float* __restrict__ A,
                                                const float* __restrict__ B,
                                                float* __restrict__ C,
                                                int M, int N, int K) {
    __shared__ __nv_bfloat16 Ah[128 * PITCH], Al[128 * PITCH];
    __shared__ __nv_bfloat16 Bh[128 * PITCH], Bl[128 * PITCH];

    const int tid = threadIdx.x;
    const int wid = tid >> 5;
    const int lane = tid & 31;
    const int bm = blockIdx.y * 128;
    const int bn = blockIdx.x * 128;
    const int wm = (wid >> 1) * 32;
    const int wn = (wid & 1) * 64;

    const uint32_t sAh = smem_u32(Ah), sAl = smem_u32(Al);
    const uint32_t sBh = smem_u32(Bh), sBl = smem_u32(Bl);

    float acc[2][8][4];
#pragma unroll
    for (int f = 0; f < 2; f++)
#pragma unroll
        for (int n = 0; n < 8; n++)
#pragma unroll
            for (int i = 0; i < 4; i++) acc[f][n][i] = 0.f;

    const int row = tid >> 1;
    const int kseg = (tid & 1) * 16;
    const float* Ap = A + (size_t)(bm + row) * K + kseg;
    const float* Bp = B + (size_t)(bn + row) * K + kseg;
    const int nch = K / 32;

    float4 ar[4], br[4];
#pragma unroll
    for (int q = 0; q < 4; q++) {
        ar[q] = *(const float4*)(Ap + q * 4);
        br[q] = *(const float4*)(Bp + q * 4);
    }

    const int a_row = (lane & 15);
    const int a_k8  = (lane >> 4) << 3;
    const int b_row = (lane & 7) + ((lane & 16) ? 8 : 0);
    const int b_k8  = (lane & 8) ? 8 : 0;

    for (int c = 0; c < nch; c++) {
        const uint32_t so = (uint32_t)row * PITCH + (uint32_t)kseg;
#pragma unroll
        for (int q = 0; q < 4; q++) {
            uint32_t h0, l0, h1, l1;
            split2(ar[q].x, ar[q].y, h0, l0);
            split2(ar[q].z, ar[q].w, h1, l1);
            *(uint2*)&Ah[so + q * 4] = make_uint2(h0, h1);
            *(uint2*)&Al[so + q * 4] = make_uint2(l0, l1);
            split2(br[q].x, br[q].y, h0, l0);
            split2(br[q].z, br[q].w, h1, l1);
            *(uint2*)&Bh[so + q * 4] = make_uint2(h0, h1);
            *(uint2*)&Bl[so + q * 4] = make_uint2(l0, l1);
        }
        __syncthreads();

        if (c + 1 < nch) {
            const float* An = Ap + (size_t)(c + 1) * 32;
            const float* Bn = Bp + (size_t)(c + 1) * 32;
#pragma unroll
            for (int q = 0; q < 4; q++) {
                ar[q] = *(const float4*)(An + q * 4);
                br[q] = *(const float4*)(Bn + q * 4);
            }
        }

#pragma unroll
        for (int ks = 0; ks < 32; ks += 16) {
            uint32_t ah[2][4], al[2][4];
#pragma unroll
            for (int f = 0; f < 2; f++) {
                uint32_t eo = ((uint32_t)(wm + f * 16 + a_row) * PITCH +
                               (uint32_t)(ks + a_k8)) * 2;
                ldm4(ah[f], sAh + eo);
                ldm4(al[f], sAl + eo);
            }
#pragma unroll
            for (int g = 0; g < 4; g++) {
                uint32_t eo = ((uint32_t)(wn + g * 16 + b_row) * PITCH +
                               (uint32_t)(ks + b_k8)) * 2;
                uint32_t th[4], tl[4];
                ldm4(th, sBh + eo);
                ldm4(tl, sBl + eo);
                uint32_t bh0[2] = {th[0], th[1]}, bh1[2] = {th[2], th[3]};
                uint32_t bl0[2] = {tl[0], tl[1]}, bl1[2] = {tl[2], tl[3]};
#pragma unroll
                for (int f = 0; f < 2; f++) {
                    mma16816(acc[f][2 * g], ah[f], bh0);
                    mma16816(acc[f][2 * g], ah[f], bl0);
                    mma16816(acc[f][2 * g], al[f], bh0);
                    mma16816(acc[f][2 * g + 1], ah[f], bh1);
                    mma16816(acc[f][2 * g + 1], ah[f], bl1);
                    mma16816(acc[f][2 * g + 1], al[f], bh1);
                }
            }
        }
        __syncthreads();
    }

    const int erow = lane >> 2;
    const int ecol = (lane & 3) * 2;
#pragma unroll
    for (int f = 0; f < 2; f++) {
        const size_t r0 = (size_t)(bm + wm + f * 16 + erow);
#pragma unroll
        for (int n = 0; n < 8; n++) {
            const size_t cc = (size_t)(bn + wn + n * 8 + ecol);
            *(float2*)&C[r0 * N + cc] = make_float2(acc[f][n][0], acc[f][n][1]);
            *(float2*)&C[(r0 + 8) * N + cc] = make_float2(acc[f][n][2], acc[f][n][3]);
        }
    }
}

// ===========================================================================
// RoPE table. sincos(x, SIN, COS) — sin first!
// ===========================================================================
__global__ void rope_table_kernel(float2* __restrict__ t) {
    int i = blockIdx.x * blockDim.x + threadIdx.x;
    int p = i & 31;
    int s = i >> 5;
    double inv = exp(-(double)p * (log(10000.0) / 32.0));
    double a = (double)s * inv;
    double sd, cd;
    sincos(a, &sd, &cd);
    t[i] = make_float2((float)cd, (float)sd);
}

// ===========================================================================
// Prep: apply RoPE to qp/kp and emit split-bf16 (hi/lo). One thread per pair.
// ===========================================================================
__global__ __launch_bounds__(256) void prep_ropesplit(
    const float* __restrict__ qp, const float* __restrict__ kp,
    const float2* __restrict__ rope_t,
    __nv_bfloat16* __restrict__ qh, __nv_bfloat16* __restrict__ ql,
    __nv_bfloat16* __restrict__ kh, __nv_bfloat16* __restrict__ kl) {
    size_t i = (size_t)blockIdx.x * 256 + threadIdx.x;   // < BSROWS*512
    int j = (int)(i & 511);
    size_t row = i >> 9;
    int pos = (int)(row & (S_ - 1));
    int pairp = j & 31;
    size_t off = row * DE + 2 * j;
    float2 cs = rope_t[pos * 32 + pairp];

    float2 x = *(const float2*)&qp[off];
    float o1 = x.x * cs.x - x.y * cs.y;
    float o2 = x.x * cs.y + x.y * cs.x;
    uint32_t hi, lo;
    split2(o1, o2, hi, lo);
    *(uint32_t*)&qh[off] = hi;
    *(uint32_t*)&ql[off] = lo;

    x = *(const float2*)&kp[off];
    o1 = x.x * cs.x - x.y * cs.y;
    o2 = x.x * cs.y + x.y * cs.x;
    split2(o1, o2, hi, lo);
    *(uint32_t*)&kh[off] = hi;
    *(uint32_t*)&kl[off] = lo;
}

// ===========================================================================
// Prep: V -> transposed split-bf16  vt[b][h][d][s]
// ===========================================================================
__global__ __launch_bounds__(256) void prep_vt(const float* __restrict__ vp,
                                               __nv_bfloat16* __restrict__ vth,
                                               __nv_bfloat16* __restrict__ vtl) {
    __shared__ float sm[64][65];
    const int tid = threadIdx.x;
    const int st = blockIdx.x, h = blockIdx.y, b = blockIdx.z;

    for (int i = tid; i < 1024; i += 256) {
        int r = i >> 4;
        int f4 = (i & 15) * 4;
        float4 v = *(const float4*)&vp[(size_t)(b * S_ + st * 64 + r) * DE + h * DH + f4];
        sm[r][f4] = v.x; sm[r][f4 + 1] = v.y; sm[r][f4 + 2] = v.z; sm[r][f4 + 3] = v.w;
    }
    __syncthreads();

    const int d = tid >> 2;
    const int ks = (tid & 3) * 16;
    uint32_t hi[8], lo[8];
#pragma unroll
    for (int j = 0; j < 8; j++)
        split2(sm[ks + 2 * j][d], sm[ks + 2 * j + 1][d], hi[j], lo[j]);

    __nv_bfloat16* dh = vth + ((size_t)((b * NH + h) * DH + d)) * S_ + st * 64 + ks;
    __nv_bfloat16* dl = vtl + ((size_t)((b * NH + h) * DH + d)) * S_ + st * 64 + ks;
    *(uint4*)&dh[0] = make_uint4(hi[0], hi[1], hi[2], hi[3]);
    *(uint4*)&dh[8] = make_uint4(hi[4], hi[5], hi[6], hi[7]);
    *(uint4*)&dl[0] = make_uint4(lo[0], lo[1], lo[2], lo[3]);
    *(uint4*)&dl[8] = make_uint4(lo[4], lo[5], lo[6], lo[7]);
}

// ===========================================================================
// Tensor-core causal flash attention. Block = 128 q rows of one (b,h),
// 8 warps x 16 rows. 64-key tiles: QK^T 3-pass split MMA, register softmax,
// P reused as A-fragments, PV 3-pass split MMA. Register prefetch of K/V.
// ===========================================================================
#define AP 72   // bf16 smem pitch (144B rows: ldmatrix conflict-free)

__global__ __launch_bounds__(256) void attn_tc(
    const __nv_bfloat16* __restrict__ qh, const __nv_bfloat16* __restrict__ ql,
    const __nv_bfloat16* __restrict__ kh, const __nv_bfloat16* __restrict__ kl,
    const __nv_bfloat16* __restrict__ vth, const __nv_bfloat16* __restrict__ vtl,
    float* __restrict__ outp) {
    __shared__ __align__(16) __nv_bfloat16 sm[256 * AP];   // 36,864 B

    const int tid = threadIdx.x;
    const int w = tid >> 5;
    const int lane = tid & 31;
    const int b = blockIdx.z, h = blockIdx.y;
    const int q0 = blockIdx.x * 128;
    const uint32_t smb = smem_u32(sm);

    // ---- stage roped split-bf16 Q tile (128 x 64), then Q fragments ----
    {
        const __nv_bfloat16* sh = qh + (size_t)(b * S_ + q0) * DE + h * DH;
        const __nv_bfloat16* sl = ql + (size_t)(b * S_ + q0) * DE + h * DH;
        for (int i = tid; i < 1024; i += 256) {
            int r = i >> 3, sg = i & 7;
            *(uint4*)&sm[r * AP + sg * 8] = *(const uint4*)&sh[(size_t)r * DE + sg * 8];
            *(uint4*)&sm[128 * AP + r * AP + sg * 8] = *(const uint4*)&sl[(size_t)r * DE + sg * 8];
        }
    }
    __syncthreads();

    uint32_t qfh[4][4], qfl[4][4];
    {
        const int arow = w * 16 + (lane & 15);
        const int ak8 = (lane >> 4) << 3;
#pragma unroll
        for (int kc = 0; kc < 4; kc++) {
            uint32_t off = (uint32_t)(arow * AP + kc * 16 + ak8) * 2;
            ldm4(qfh[kc], smb + off);
            ldm4(qfl[kc], smb + 128 * AP * 2 + off);
        }
    }

    float oacc[8][4];
#pragma unroll
    for (int n = 0; n < 8; n++)
#pragma unroll
        for (int i = 0; i < 4; i++) oacc[n][i] = 0.f;
    float m0 = -1e30f, m1 = -1e30f, l0 = 0.f, l1 = 0.f;

    const int nkt = 2 * blockIdx.x + 2;
    const int row0 = q0 + w * 16 + (lane >> 2);
    const int brow = (lane & 7) + ((lane & 16) ? 8 : 0);
    const int bk8 = (lane & 8) ? 8 : 0;

    const __nv_bfloat16* Kh = kh + (size_t)b * S_ * DE + h * DH;
    const __nv_bfloat16* Kl = kl + (size_t)b * S_ * DE + h * DH;
    const __nv_bfloat16* Vh = vth + (size_t)(b * NH + h) * DH * S_;
    const __nv_bfloat16* Vl = vtl + (size_t)(b * NH + h) * DH * S_;

    // prefetch tile 0 (per thread: 2 uint4 per array)
    const int prow = tid >> 2;            // for K arrays: i>>3 pattern below
    uint4 pre[8];
    {
        const int k0 = 0;
#pragma unroll
        for (int j = 0; j < 2; j++) {
            int i = tid + 256 * j;
            int r = i >> 3, sg = i & 7;
            pre[0 + j] = *(const uint4*)&Kh[(size_t)(k0 + r) * DE + sg * 8];
            pre[2 + j] = *(const uint4*)&Kl[(size_t)(k0 + r) * DE + sg * 8];
            pre[4 + j] = *(const uint4*)&Vh[(size_t)r * S_ + k0 + sg * 8];
            pre[6 + j] = *(const uint4*)&Vl[(size_t)r * S_ + k0 + sg * 8];
        }
    }
    (void)prow;

    for (int kt = 0; kt < nkt; kt++) {
        const int k0 = kt * 64;
        __syncthreads();   // Q frags read (first iter) / prior compute done
#pragma unroll
        for (int j = 0; j < 2; j++) {
            int i = tid + 256 * j;
            int r = i >> 3, sg = i & 7;
            *(uint4*)&sm[r * AP + sg * 8] = pre[0 + j];
            *(uint4*)&sm[64 * AP + r * AP + sg * 8] = pre[2 + j];
            *(uint4*)&sm[128 * AP + r * AP + sg * 8] = pre[4 + j];
            *(uint4*)&sm[192 * AP + r * AP + sg * 8] = pre[6 + j];
        }
        __syncthreads();

        if (kt + 1 < nkt) {
            const int kn = k0 + 64;
#pragma unroll
            for (int j = 0; j < 2; j++) {
                int i = tid + 256 * j;
                int r = i >> 3, sg = i & 7;
                pre[0 + j] = *(const uint4*)&Kh[(size_t)(kn + r) * DE + sg * 8];
                pre[2 + j] = *(const uint4*)&Kl[(size_t)(kn + r) * DE + sg * 8];
                pre[4 + j] = *(const uint4*)&Vh[(size_t)r * S_ + kn + sg * 8];
                pre[6 + j] = *(const uint4*)&Vl[(size_t)r * S_ + kn + sg * 8];
            }
        }

        // ---- S = Q K^T (split 3-pass) ----
        float sacc[8][4];
#pragma unroll
        for (int n = 0; n < 8; n++)
#pragma unroll
            for (int i = 0; i < 4; i++) sacc[n][i] = 0.f;

#pragma unroll
        for (int kc = 0; kc < 4; kc++)
#pragma unroll
            for (int g = 0; g < 4; g++) {
                uint32_t off = (uint32_t)((g * 16 + brow) * AP + kc * 16 + bk8) * 2;
                uint32_t th[4], tl[4];
                ldm4(th, smb + off);
                ldm4(tl, smb + 64 * AP * 2 + off);
                uint32_t bh0[2] = {th[0], th[1]}, bh1[2] = {th[2], th[3]};
                uint32_t bl0[2] = {tl[0], tl[1]}, bl1[2] = {tl[2], tl[3]};
                mma16816(sacc[2 * g], qfh[kc], bh0);
                mma16816(sacc[2 * g], qfh[kc], bl0);
                mma16816(sacc[2 * g], qfl[kc], bh0);
                mma16816(sacc[2 * g + 1], qfh[kc], bh1);
                mma16816(sacc[2 * g + 1], qfh[kc], bl1);
                mma16816(sacc[2 * g + 1], qfl[kc], bh1);
            }

        // ---- scale + causal mask ----
        const bool diag = (kt >= nkt - 2);
#pragma unroll
        for (int n = 0; n < 8; n++) {
            int col = k0 + n * 8 + (lane & 3) * 2;
#pragma unroll
            for (int i = 0; i < 4; i++) sacc[n][i] *= 0.03125f;
            if (diag) {
                if (col > row0) sacc[n][0] = -1e30f;
                if (col + 1 > row0) sacc[n][1] = -1e30f;
                if (col > row0 + 8) sacc[n][2] = -1e30f;
                if (col + 1 > row0 + 8) sacc[n][3] = -1e30f;
            }
        }

        // ---- online softmax (rows row0, row0+8) ----
        float mt0 = -1e30f, mt1 = -1e30f;
#pragma unroll
        for (int n = 0; n < 8; n++) {
            mt0 = fmaxf(mt0, fmaxf(sacc[n][0], sacc[n][1]));
            mt1 = fmaxf(mt1, fmaxf(sacc[n][2], sacc[n][3]));
        }
        mt0 = fmaxf(mt0, __shfl_xor_sync(0xffffffffu, mt0, 1));
        mt0 = fmaxf(mt0, __shfl_xor_sync(0xffffffffu, mt0, 2));
        mt1 = fmaxf(mt1, __shfl_xor_sync(0xffffffffu, mt1, 1));
        mt1 = fmaxf(mt1, __shfl_xor_sync(0xffffffffu, mt1, 2));

        float mn0 = fmaxf(m0, mt0), mn1 = fmaxf(m1, mt1);
        float a0 = __expf(m0 - mn0), a1 = __expf(m1 - mn1);
        m0 = mn0; m1 = mn1;

        float s0 = 0.f, s1 = 0.f;
#pragma unroll
        for (int n = 0; n < 8; n++) {
            sacc[n][0] = __expf(sacc[n][0] - mn0);
            sacc[n][1] = __expf(sacc[n][1] - mn0);
            sacc[n][2] = __expf(sacc[n][2] - mn1);
            sacc[n][3] = __expf(sacc[n][3] - mn1);
            s0 += sacc[n][0] + sacc[n][1];
            s1 += sacc[n][2] + sacc[n][3];
        }
        s0 += __shfl_xor_sync(0xffffffffu, s0, 1);
        s0 += __shfl_xor_sync(0xffffffffu, s0, 2);
        s1 += __shfl_xor_sync(0xffffffffu, s1, 1);
        s1 += __shfl_xor_sync(0xffffffffu, s1, 2);
        l0 = l0 * a0 + s0;
        l1 = l1 * a1 + s1;
#pragma unroll
        for (int n = 0; n < 8; n++) {
            oacc[n][0] *= a0; oacc[n][1] *= a0;
            oacc[n][2] *= a1; oacc[n][3] *= a1;
        }

        // ---- O += P V (split 3-pass); P packed from registers ----
#pragma unroll
        for (int kc = 0; kc < 4; kc++) {
            uint32_t pah[4], pal[4];
            split2(sacc[2 * kc][0], sacc[2 * kc][1], pah[0], pal[0]);
            split2(sacc[2 * kc][2], sacc[2 * kc][3], pah[1], pal[1]);
            split2(sacc[2 * kc + 1][0], sacc[2 * kc + 1][1], pah[2], pal[2]);
            split2(sacc[2 * kc + 1][2], sacc[2 * kc + 1][3], pah[3], pal[3]);
#pragma unroll
            for (int g = 0; g < 4; g++) {
                uint32_t off = (uint32_t)((g * 16 + brow) * AP + kc * 16 + bk8) * 2;
                uint32_t th[4], tl[4];
                ldm4(th, smb + 128 * AP * 2 + off);
                ldm4(tl, smb + 192 * AP * 2 + off);
                uint32_t bh0[2] = {th[0], th[1]}, bh1[2] = {th[2], th[3]};
                uint32_t bl0[2] = {tl[0], tl[1]}, bl1[2] = {tl[2], tl[3]};
                mma16816(oacc[2 * g], pah, bh0);
                mma16816(oacc[2 * g], pah, bl0);
                mma16816(oacc[2 * g], pal, bh0);
                mma16816(oacc[2 * g + 1], pah, bh1);
                mma16816(oacc[2 * g + 1], pah, bl1);
                mma16816(oacc[2 * g + 1], pal, bh1);
            }
        }
    }

    // ---- epilogue ----
    const float inv0 = 1.0f / l0, inv1 = 1.0f / l1;
    const size_t gr0 = (size_t)(b * S_ + row0);
#pragma unroll
    for (int n = 0; n < 8; n++) {
        const size_t cc = (size_t)(h * DH + n * 8 + (lane & 3) * 2);
        *(float2*)&outp[gr0 * DE + cc] = make_float2(oacc[n][0] * inv0, oacc[n][1] * inv0);
        *(float2*)&outp[(gr0 + 8) * DE + cc] = make_float2(oacc[n][2] * inv1, oacc[n][3] * inv1);
    }
}

// ===========================================================================
extern "C" void kernel_launch(void* const* d_in, const int* in_sizes, int n_in,
                              void* d_out, int out_size) {
    const float* q  = (const float*)d_in[0];
    const float* k  = (const float*)d_in[1];
    const float* v  = (const float*)d_in[2];
    const float* Wq = (const float*)d_in[3];
    const float* Wk = (const float*)d_in[4];
    const float* Wv = (const float*)d_in[5];
    const float* Wo = (const float*)d_in[6];
    float* out = (float*)d_out;

    float *qp, *kp, *vp, *at;
    float2* rope_t;
    __nv_bfloat16 *qh, *ql, *kh, *kl, *vth, *vtl;
    cudaGetSymbolAddress((void**)&qp, g_qp);
    cudaGetSymbolAddress((void**)&kp, g_kp);
    cudaGetSymbolAddress((void**)&vp, g_vp);
    cudaGetSymbolAddress((void**)&at, g_at);
    cudaGetSymbolAddress((void**)&rope_t, g_rope);
    cudaGetSymbolAddress((void**)&qh, g_qh);
    cudaGetSymbolAddress((void**)&ql, g_ql);
    cudaGetSymbolAddress((void**)&kh, g_kh);
    cudaGetSymbolAddress((void**)&kl, g_kl);
    cudaGetSymbolAddress((void**)&vth, g_vth);
    cudaGetSymbolAddress((void**)&vtl, g_vtl);

    rope_table_kernel<<<(S_ * 32) / 256, 256>>>(rope_t);

    dim3 gq(DE / 128, BSROWS / 128);  // (8, 64)
    gemm_mma<<<gq, 256>>>(q, Wq, qp, BSROWS, DE, 2 * DE);
    gemm_mma<<<gq, 256>>>(k, Wk, kp, BSROWS, DE, 2 * DE);
    gemm_mma<<<gq, 256>>>(v, Wv, vp, BSROWS, DE, DE);

    prep_ropesplit<<<(BSROWS * 512) / 256, 256>>>(qp, kp, rope_t, qh, ql, kh, kl);
    prep_vt<<<dim3(S_ / 64, NH, B_), 256>>>(vp, vth, vtl);

    attn_tc<<<dim3(S_ / 128, NH, B_), 256>>>(qh, ql, kh, kl, vth, vtl, at);

    gemm_mma<<<gq, 256>>>(at, Wo, out, BSROWS, DE, DE);
}

// round 11
// speedup vs baseline: 2.9464x; 1.0124x over previous
#include <cuda_runtime.h>
#include <cuda_bf16.h>
#include <math.h>
#include <stdint.h>

#define B_    4
#define S_    2048
#define DE    1024
#define NH    16
#define DH    64
#define BSROWS (B_ * S_)   // 8192

// fp32 scratch
__device__ float g_qp[(size_t)BSROWS * DE];
__device__ float g_kp[(size_t)BSROWS * DE];
__device__ float g_vp[(size_t)BSROWS * DE];
__device__ float g_at[(size_t)BSROWS * DE];
__device__ float2 g_rope[(size_t)S_ * 32];
// split-bf16 attention operands (hi/lo); vt is [b][h][d][s]
__device__ __nv_bfloat16 g_qh[(size_t)BSROWS * DE];
__device__ __nv_bfloat16 g_ql[(size_t)BSROWS * DE];
__device__ __nv_bfloat16 g_kh[(size_t)BSROWS * DE];
__device__ __nv_bfloat16 g_kl[(size_t)BSROWS * DE];
__device__ __nv_bfloat16 g_vth[(size_t)BSROWS * DE];
__device__ __nv_bfloat16 g_vtl[(size_t)BSROWS * DE];

// ===========================================================================
// Helpers
// ===========================================================================
__device__ __forceinline__ uint32_t smem_u32(const void* p) {
    uint32_t a;
    asm("{ .reg .u64 t; cvta.to.shared.u64 t, %1; cvt.u32.u64 %0, t; }"
        : "=r"(a) : "l"(p));
    return a;
}
__device__ __forceinline__ void ldm4(uint32_t* r, uint32_t addr) {
    asm volatile("ldmatrix.sync.aligned.m8n8.x4.shared.b16 {%0,%1,%2,%3}, [%4];"
                 : "=r"(r[0]), "=r"(r[1]), "=r"(r[2]), "=r"(r[3]) : "r"(addr));
}
__device__ __forceinline__ void mma16816(float* d, const uint32_t* a, const uint32_t* b) {
    asm volatile(
        "mma.sync.aligned.m16n8k16.row.col.f32.bf16.bf16.f32 "
        "{%0,%1,%2,%3}, {%4,%5,%6,%7}, {%8,%9}, {%0,%1,%2,%3};"
        : "+f"(d[0]), "+f"(d[1]), "+f"(d[2]), "+f"(d[3])
        : "r"(a[0]), "r"(a[1]), "r"(a[2]), "r"(a[3]), "r"(b[0]), "r"(b[1]));
}
__device__ __forceinline__ uint32_t pk_bf2(float a, float b) {
    __nv_bfloat162 t = __floats2bfloat162_rn(a, b);
    return *reinterpret_cast<uint32_t*>(&t);
}
__device__ __forceinline__ void split2(float a, float b, uint32_t& hi, uint32_t& lo) {
    float ha = __bfloat162float(__float2bfloat16_rn(a));
    float hb = __bfloat162float(__float2bfloat16_rn(b));
    hi = pk_bf2(ha, hb);
    lo = pk_bf2(a - ha, b - hb);
}
__device__ __forceinline__ void cp16(uint32_t dst, const void* src) {
    asm volatile("cp.async.cg.shared.global [%0], [%1], 16;"
                 :: "r"(dst), "l"(src) : "memory");
}
#define CP_COMMIT() asm volatile("cp.async.commit_group;" ::: "memory")
#define CP_WAIT(N)  asm volatile("cp.async.wait_group %0;" :: "n"(N) : "memory")

// ===========================================================================
// Split-bf16 tensor-core GEMM (round-9/10, PASS — unchanged)
// ===========================================================================
#define PITCH 40

__global__ __launch_bounds__(256) void gemm_mma(const float* __restrict__ A,
                                                const float* __restrict__ B,
                                                float* __restrict__ C,
                                                int M, int N, int K) {
    __shared__ __nv_bfloat16 Ah[128 * PITCH], Al[128 * PITCH];
    __shared__ __nv_bfloat16 Bh[128 * PITCH], Bl[128 * PITCH];

    const int tid = threadIdx.x;
    const int wid = tid >> 5;
    const int lane = tid & 31;
    const int bm = blockIdx.y * 128;
    const int bn = blockIdx.x * 128;
    const int wm = (wid >> 1) * 32;
    const int wn = (wid & 1) * 64;

    const uint32_t sAh = smem_u32(Ah), sAl = smem_u32(Al);
    const uint32_t sBh = smem_u32(Bh), sBl = smem_u32(Bl);

    float acc[2][8][4];
#pragma unroll
    for (int f = 0; f < 2; f++)
#pragma unroll
        for (int n = 0; n < 8; n++)
#pragma unroll
            for (int i = 0; i < 4; i++) acc[f][n][i] = 0.f;

    const int row = tid >> 1;
    const int kseg = (tid & 1) * 16;
    const float* Ap = A + (size_t)(bm + row) * K + kseg;
    const float* Bp = B + (size_t)(bn + row) * K + kseg;
    const int nch = K / 32;

    float4 ar[4], br[4];
#pragma unroll
    for (int q = 0; q < 4; q++) {
        ar[q] = *(const float4*)(Ap + q * 4);
        br[q] = *(const float4*)(Bp + q * 4);
    }

    const int a_row = (lane & 15);
    const int a_k8  = (lane >> 4) << 3;
    const int b_row = (lane & 7) + ((lane & 16) ? 8 : 0);
    const int b_k8  = (lane & 8) ? 8 : 0;

    for (int c = 0; c < nch; c++) {
        const uint32_t so = (uint32_t)row * PITCH + (uint32_t)kseg;
#pragma unroll
        for (int q = 0; q < 4; q++) {
            uint32_t h0, l0, h1, l1;
            split2(ar[q].x, ar[q].y, h0, l0);
            split2(ar[q].z, ar[q].w, h1, l1);
            *(uint2*)&Ah[so + q * 4] = make_uint2(h0, h1);
            *(uint2*)&Al[so + q * 4] = make_uint2(l0, l1);
            split2(br[q].x, br[q].y, h0, l0);
            split2(br[q].z, br[q].w, h1, l1);
            *(uint2*)&Bh[so + q * 4] = make_uint2(h0, h1);
            *(uint2*)&Bl[so + q * 4] = make_uint2(l0, l1);
        }
        __syncthreads();

        if (c + 1 < nch) {
            const float* An = Ap + (size_t)(c + 1) * 32;
            const float* Bn = Bp + (size_t)(c + 1) * 32;
#pragma unroll
            for (int q = 0; q < 4; q++) {
                ar[q] = *(const float4*)(An + q * 4);
                br[q] = *(const float4*)(Bn + q * 4);
            }
        }

#pragma unroll
        for (int ks = 0; ks < 32; ks += 16) {
            uint32_t ah[2][4], al[2][4];
#pragma unroll
            for (int f = 0; f < 2; f++) {
                uint32_t eo = ((uint32_t)(wm + f * 16 + a_row) * PITCH +
                               (uint32_t)(ks + a_k8)) * 2;
                ldm4(ah[f], sAh + eo);
                ldm4(al[f], sAl + eo);
            }
#pragma unroll
            for (int g = 0; g < 4; g++) {
                uint32_t eo = ((uint32_t)(wn + g * 16 + b_row) * PITCH +
                               (uint32_t)(ks + b_k8)) * 2;
                uint32_t th[4], tl[4];
                ldm4(th, sBh + eo);
                ldm4(tl, sBl + eo);
                uint32_t bh0[2] = {th[0], th[1]}, bh1[2] = {th[2], th[3]};
                uint32_t bl0[2] = {tl[0], tl[1]}, bl1[2] = {tl[2], tl[3]};
#pragma unroll
                for (int f = 0; f < 2; f++) {
                    mma16816(acc[f][2 * g], ah[f], bh0);
                    mma16816(acc[f][2 * g], ah[f], bl0);
                    mma16816(acc[f][2 * g], al[f], bh0);
                    mma16816(acc[f][2 * g + 1], ah[f], bh1);
                    mma16816(acc[f][2 * g + 1], ah[f], bl1);
                    mma16816(acc[f][2 * g + 1], al[f], bh1);
                }
            }
        }
        __syncthreads();
    }

    const int erow = lane >> 2;
    const int ecol = (lane & 3) * 2;
#pragma unroll
    for (int f = 0; f < 2; f++) {
        const size_t r0 = (size_t)(bm + wm + f * 16 + erow);
#pragma unroll
        for (int n = 0; n < 8; n++) {
            const size_t cc = (size_t)(bn + wn + n * 8 + ecol);
            *(float2*)&C[r0 * N + cc] = make_float2(acc[f][n][0], acc[f][n][1]);
            *(float2*)&C[(r0 + 8) * N + cc] = make_float2(acc[f][n][2], acc[f][n][3]);
        }
    }
}

// ===========================================================================
// RoPE table. sincos(x, SIN, COS) — sin first!
// ===========================================================================
__global__ void rope_table_kernel(float2* __restrict__ t) {
    int i = blockIdx.x * blockDim.x + threadIdx.x;
    int p = i & 31;
    int s = i >> 5;
    double inv = exp(-(double)p * (log(10000.0) / 32.0));
    double a = (double)s * inv;
    double sd, cd;
    sincos(a, &sd, &cd);
    t[i] = make_float2((float)cd, (float)sd);
}

// ===========================================================================
// Prep: RoPE + split-bf16. Q additionally pre-scaled by 1/32 (softmax scale).
// ===========================================================================
__global__ __launch_bounds__(256) void prep_ropesplit(
    const float* __restrict__ qp, const float* __restrict__ kp,
    const float2* __restrict__ rope_t,
    __nv_bfloat16* __restrict__ qh, __nv_bfloat16* __restrict__ ql,
    __nv_bfloat16* __restrict__ kh, __nv_bfloat16* __restrict__ kl) {
    size_t i = (size_t)blockIdx.x * 256 + threadIdx.x;   // < BSROWS*512
    int j = (int)(i & 511);
    size_t row = i >> 9;
    int pos = (int)(row & (S_ - 1));
    int pairp = j & 31;
    size_t off = row * DE + 2 * j;
    float2 cs = rope_t[pos * 32 + pairp];

    float2 x = *(const float2*)&qp[off];
    float o1 = (x.x * cs.x - x.y * cs.y) * 0.03125f;
    float o2 = (x.x * cs.y + x.y * cs.x) * 0.03125f;
    uint32_t hi, lo;
    split2(o1, o2, hi, lo);
    *(uint32_t*)&qh[off] = hi;
    *(uint32_t*)&ql[off] = lo;

    x = *(const float2*)&kp[off];
    o1 = x.x * cs.x - x.y * cs.y;
    o2 = x.x * cs.y + x.y * cs.x;
    split2(o1, o2, hi, lo);
    *(uint32_t*)&kh[off] = hi;
    *(uint32_t*)&kl[off] = lo;
}

// ===========================================================================
// Prep: V -> transposed split-bf16  vt[b][h][d][s]
// ===========================================================================
__global__ __launch_bounds__(256) void prep_vt(const float* __restrict__ vp,
                                               __nv_bfloat16* __restrict__ vth,
                                               __nv_bfloat16* __restrict__ vtl) {
    __shared__ float sm[64][65];
    const int tid = threadIdx.x;
    const int st = blockIdx.x, h = blockIdx.y, b = blockIdx.z;

    for (int i = tid; i < 1024; i += 256) {
        int r = i >> 4;
        int f4 = (i & 15) * 4;
        float4 v = *(const float4*)&vp[(size_t)(b * S_ + st * 64 + r) * DE + h * DH + f4];
        sm[r][f4] = v.x; sm[r][f4 + 1] = v.y; sm[r][f4 + 2] = v.z; sm[r][f4 + 3] = v.w;
    }
    __syncthreads();

    const int d = tid >> 2;
    const int ks = (tid & 3) * 16;
    uint32_t hi[8], lo[8];
#pragma unroll
    for (int j = 0; j < 8; j++)
        split2(sm[ks + 2 * j][d], sm[ks + 2 * j + 1][d], hi[j], lo[j]);

    __nv_bfloat16* dh = vth + ((size_t)((b * NH + h) * DH + d)) * S_ + st * 64 + ks;
    __nv_bfloat16* dl = vtl + ((size_t)((b * NH + h) * DH + d)) * S_ + st * 64 + ks;
    *(uint4*)&dh[0] = make_uint4(hi[0], hi[1], hi[2], hi[3]);
    *(uint4*)&dh[8] = make_uint4(hi[4], hi[5], hi[6], hi[7]);
    *(uint4*)&dl[0] = make_uint4(lo[0], lo[1], lo[2], lo[3]);
    *(uint4*)&dl[8] = make_uint4(lo[4], lo[5], lo[6], lo[7]);
}

// ===========================================================================
// Tensor-core causal flash attention, cp.async 3-buffer ring pipeline.
// Block = 128 q rows of one (b,h), 8 warps x 16 rows. Per 64-key tile:
// QK^T split-MMA, register online softmax, P->A frags, PV split-MMA.
// K/V (hi/lo) tiles stream global->smem via cp.async, 2 tiles ahead.
// ===========================================================================
#define AP 72                         // bf16 smem pitch
#define BUFE (256 * AP)               // elements per ring buffer
#define ATTN_SMEM (3 * BUFE * 2)      // 110,592 B

__global__ __launch_bounds__(256) void attn_tc(
    const __nv_bfloat16* __restrict__ qh, const __nv_bfloat16* __restrict__ ql,
    const __nv_bfloat16* __restrict__ kh, const __nv_bfloat16* __restrict__ kl,
    const __nv_bfloat16* __restrict__ vth, const __nv_bfloat16* __restrict__ vtl,
    float* __restrict__ outp) {
    extern __shared__ __align__(16) __nv_bfloat16 sm[];

    const int tid = threadIdx.x;
    const int w = tid >> 5;
    const int lane = tid & 31;
    const int b = blockIdx.z, h = blockIdx.y;
    const int q0 = blockIdx.x * 128;
    const uint32_t smb = smem_u32(sm);
    const int nkt = 2 * blockIdx.x + 2;

    const __nv_bfloat16* Kh = kh + (size_t)b * S_ * DE + h * DH;
    const __nv_bfloat16* Kl = kl + (size_t)b * S_ * DE + h * DH;
    const __nv_bfloat16* Vh = vth + (size_t)(b * NH + h) * DH * S_;
    const __nv_bfloat16* Vl = vtl + (size_t)(b * NH + h) * DH * S_;

    const int cr = tid >> 3;        // 0..31 (row base for cp.async, j adds 32)
    const int csg = tid & 7;        // 16B segment

    // --- issue tiles 0 and 1 into ring buffers 0, 1 ---
#pragma unroll
    for (int t0 = 0; t0 < 2; t0++) {
        const int k0 = t0 * 64;
        const uint32_t base = smb + (uint32_t)t0 * BUFE * 2;
#pragma unroll
        for (int j = 0; j < 2; j++) {
            int r = cr + 32 * j;
            uint32_t dof = ((uint32_t)r * AP + csg * 8) * 2;
            cp16(base + dof, Kh + (size_t)(k0 + r) * DE + csg * 8);
            cp16(base + 64 * AP * 2 + dof, Kl + (size_t)(k0 + r) * DE + csg * 8);
            cp16(base + 128 * AP * 2 + dof, Vh + (size_t)r * S_ + k0 + csg * 8);
            cp16(base + 192 * AP * 2 + dof, Vl + (size_t)r * S_ + k0 + csg * 8);
        }
        CP_COMMIT();
    }

    // --- stage Q (hi/lo) into ring buffer 2, extract fragments ---
    {
        __nv_bfloat16* qs = sm + 2 * BUFE;
        const __nv_bfloat16* sh = qh + (size_t)(b * S_ + q0) * DE + h * DH;
        const __nv_bfloat16* sl = ql + (size_t)(b * S_ + q0) * DE + h * DH;
#pragma unroll
        for (int j = 0; j < 4; j++) {
            int i = tid + 256 * j;
            int r = i >> 3, sg = i & 7;
            *(uint4*)&qs[r * AP + sg * 8] = *(const uint4*)&sh[(size_t)r * DE + sg * 8];
            *(uint4*)&qs[128 * AP + r * AP + sg * 8] =
                *(const uint4*)&sl[(size_t)r * DE + sg * 8];
        }
    }
    __syncthreads();

    uint32_t qfh[4][4], qfl[4][4];
    {
        const uint32_t qb = smb + 2 * BUFE * 2;
        const int arow = w * 16 + (lane & 15);
        const int ak8 = (lane >> 4) << 3;
#pragma unroll
        for (int kc = 0; kc < 4; kc++) {
            uint32_t off = (uint32_t)(arow * AP + kc * 16 + ak8) * 2;
            ldm4(qfh[kc], qb + off);
            ldm4(qfl[kc], qb + 128 * AP * 2 + off);
        }
    }
    __syncthreads();

    float oacc[8][4];
#pragma unroll
    for (int n = 0; n < 8; n++)
#pragma unroll
        for (int i = 0; i < 4; i++) oacc[n][i] = 0.f;
    float m0 = -1e30f, m1 = -1e30f, l0 = 0.f, l1 = 0.f;

    const int row0 = q0 + w * 16 + (lane >> 2);
    const int brow = (lane & 7) + ((lane & 16) ? 8 : 0);
    const int bk8 = (lane & 8) ? 8 : 0;

    int bufsel = 0;   // kt % 3
    for (int kt = 0; kt < nkt; kt++) {
        const int k0 = kt * 64;
        if (kt + 2 < nkt) { CP_WAIT(1); } else { CP_WAIT(0); }
        __syncthreads();

        // issue tile kt+2 into the buffer computed at kt-1 (protected by sync)
        if (kt + 2 < nkt) {
            const int kn = k0 + 128;
            int nb = bufsel + 2;
            if (nb >= 3) nb -= 3;
            const uint32_t base = smb + (uint32_t)nb * BUFE * 2;
#pragma unroll
            for (int j = 0; j < 2; j++) {
                int r = cr + 32 * j;
                uint32_t dof = ((uint32_t)r * AP + csg * 8) * 2;
                cp16(base + dof, Kh + (size_t)(kn + r) * DE + csg * 8);
                cp16(base + 64 * AP * 2 + dof, Kl + (size_t)(kn + r) * DE + csg * 8);
                cp16(base + 128 * AP * 2 + dof, Vh + (size_t)r * S_ + kn + csg * 8);
                cp16(base + 192 * AP * 2 + dof, Vl + (size_t)r * S_ + kn + csg * 8);
            }
            CP_COMMIT();
        }

        const uint32_t kb = smb + (uint32_t)bufsel * BUFE * 2;

        // ---- S = Q K^T (split 3-pass); Q pre-scaled by 1/32 ----
        float sacc[8][4];
#pragma unroll
        for (int n = 0; n < 8; n++)
#pragma unroll
            for (int i = 0; i < 4; i++) sacc[n][i] = 0.f;

#pragma unroll
        for (int kc = 0; kc < 4; kc++)
#pragma unroll
            for (int g = 0; g < 4; g++) {
                uint32_t off = (uint32_t)((g * 16 + brow) * AP + kc * 16 + bk8) * 2;
                uint32_t th[4], tl[4];
                ldm4(th, kb + off);
                ldm4(tl, kb + 64 * AP * 2 + off);
                uint32_t bh0[2] = {th[0], th[1]}, bh1[2] = {th[2], th[3]};
                uint32_t bl0[2] = {tl[0], tl[1]}, bl1[2] = {tl[2], tl[3]};
                mma16816(sacc[2 * g], qfh[kc], bh0);
                mma16816(sacc[2 * g], qfh[kc], bl0);
                mma16816(sacc[2 * g], qfl[kc], bh0);
                mma16816(sacc[2 * g + 1], qfh[kc], bh1);
                mma16816(sacc[2 * g + 1], qfh[kc], bl1);
                mma16816(sacc[2 * g + 1], qfl[kc], bh1);
            }

        // ---- causal mask (only last two tiles can straddle) ----
        if (kt >= nkt - 2) {
#pragma unroll
            for (int n = 0; n < 8; n++) {
                int col = k0 + n * 8 + (lane & 3) * 2;
                if (col > row0) sacc[n][0] = -1e30f;
                if (col + 1 > row0) sacc[n][1] = -1e30f;
                if (col > row0 + 8) sacc[n][2] = -1e30f;
                if (col + 1 > row0 + 8) sacc[n][3] = -1e30f;
            }
        }

        // ---- online softmax (rows row0, row0+8) ----
        float mt0 = -1e30f, mt1 = -1e30f;
#pragma unroll
        for (int n = 0; n < 8; n++) {
            mt0 = fmaxf(mt0, fmaxf(sacc[n][0], sacc[n][1]));
            mt1 = fmaxf(mt1, fmaxf(sacc[n][2], sacc[n][3]));
        }
        mt0 = fmaxf(mt0, __shfl_xor_sync(0xffffffffu, mt0, 1));
        mt0 = fmaxf(mt0, __shfl_xor_sync(0xffffffffu, mt0, 2));
        mt1 = fmaxf(mt1, __shfl_xor_sync(0xffffffffu, mt1, 1));
        mt1 = fmaxf(mt1, __shfl_xor_sync(0xffffffffu, mt1, 2));

        float mn0 = fmaxf(m0, mt0), mn1 = fmaxf(m1, mt1);
        float a0 = __expf(m0 - mn0), a1 = __expf(m1 - mn1);
        m0 = mn0; m1 = mn1;

        float s0 = 0.f, s1 = 0.f;
#pragma unroll
        for (int n = 0; n < 8; n++) {
            sacc[n][0] = __expf(sacc[n][0] - mn0);
            sacc[n][1] = __expf(sacc[n][1] - mn0);
            sacc[n][2] = __expf(sacc[n][2] - mn1);
            sacc[n][3] = __expf(sacc[n][3] - mn1);
            s0 += sacc[n][0] + sacc[n][1];
            s1 += sacc[n][2] + sacc[n][3];
        }
        s0 += __shfl_xor_sync(0xffffffffu, s0, 1);
        s0 += __shfl_xor_sync(0xffffffffu, s0, 2);
        s1 += __shfl_xor_sync(0xffffffffu, s1, 1);
        s1 += __shfl_xor_sync(0xffffffffu, s1, 2);
        l0 = l0 * a0 + s0;
        l1 = l1 * a1 + s1;
#pragma unroll
        for (int n = 0; n < 8; n++) {
            oacc[n][0] *= a0; oacc[n][1] *= a0;
            oacc[n][2] *= a1; oacc[n][3] *= a1;
        }

        // ---- O += P V (split 3-pass); P packed from registers ----
#pragma unroll
        for (int kc = 0; kc < 4; kc++) {
            uint32_t pah[4], pal[4];
            split2(sacc[2 * kc][0], sacc[2 * kc][1], pah[0], pal[0]);
            split2(sacc[2 * kc][2], sacc[2 * kc][3], pah[1], pal[1]);
            split2(sacc[2 * kc + 1][0], sacc[2 * kc + 1][1], pah[2], pal[2]);
            split2(sacc[2 * kc + 1][2], sacc[2 * kc + 1][3], pah[3], pal[3]);
#pragma unroll
            for (int g = 0; g < 4; g++) {
                uint32_t off = (uint32_t)((g * 16 + brow) * AP + kc * 16 + bk8) * 2;
                uint32_t th[4], tl[4];
                ldm4(th, kb + 128 * AP * 2 + off);
                ldm4(tl, kb + 192 * AP * 2 + off);
                uint32_t bh0[2] = {th[0], th[1]}, bh1[2] = {th[2], th[3]};
                uint32_t bl0[2] = {tl[0], tl[1]}, bl1[2] = {tl[2], tl[3]};
                mma16816(oacc[2 * g], pah, bh0);
                mma16816(oacc[2 * g], pah, bl0);
                mma16816(oacc[2 * g], pal, bh0);
                mma16816(oacc[2 * g + 1], pah, bh1);
                mma16816(oacc[2 * g + 1], pah, bl1);
                mma16816(oacc[2 * g + 1], pal, bh1);
            }
        }

        if (++bufsel == 3) bufsel = 0;
    }

    // ---- epilogue ----
    const float inv0 = 1.0f / l0, inv1 = 1.0f / l1;
    const size_t gr0 = (size_t)(b * S_ + row0);
#pragma unroll
    for (int n = 0; n < 8; n++) {
        const size_t cc = (size_t)(h * DH + n * 8 + (lane & 3) * 2);
        *(float2*)&outp[gr0 * DE + cc] = make_float2(oacc[n][0] * inv0, oacc[n][1] * inv0);
        *(float2*)&outp[(gr0 + 8) * DE + cc] = make_float2(oacc[n][2] * inv1, oacc[n][3] * inv1);
    }
}

// ===========================================================================
extern "C" void kernel_launch(void* const* d_in, const int* in_sizes, int n_in,
                              void* d_out, int out_size) {
    const float* q  = (const float*)d_in[0];
    const float* k  = (const float*)d_in[1];
    const float* v  = (const float*)d_in[2];
    const float* Wq = (const float*)d_in[3];
    const float* Wk = (const float*)d_in[4];
    const float* Wv = (const float*)d_in[5];
    const float* Wo = (const float*)d_in[6];
    float* out = (float*)d_out;

    float *qp, *kp, *vp, *at;
    float2* rope_t;
    __nv_bfloat16 *qh, *ql, *kh, *kl, *vth, *vtl;
    cudaGetSymbolAddress((void**)&qp, g_qp);
    cudaGetSymbolAddress((void**)&kp, g_kp);
    cudaGetSymbolAddress((void**)&vp, g_vp);
    cudaGetSymbolAddress((void**)&at, g_at);
    cudaGetSymbolAddress((void**)&rope_t, g_rope);
    cudaGetSymbolAddress((void**)&qh, g_qh);
    cudaGetSymbolAddress((void**)&ql, g_ql);
    cudaGetSymbolAddress((void**)&kh, g_kh);
    cudaGetSymbolAddress((void**)&kl, g_kl);
    cudaGetSymbolAddress((void**)&vth, g_vth);
    cudaGetSymbolAddress((void**)&vtl, g_vtl);

    cudaFuncSetAttribute(attn_tc, cudaFuncAttributeMaxDynamicSharedMemorySize,
                         ATTN_SMEM);

    rope_table_kernel<<<(S_ * 32) / 256, 256>>>(rope_t);

    dim3 gq(DE / 128, BSROWS / 128);  // (8, 64)
    gemm_mma<<<gq, 256>>>(q, Wq, qp, BSROWS, DE, 2 * DE);
    gemm_mma<<<gq, 256>>>(k, Wk, kp, BSROWS, DE, 2 * DE);
    gemm_mma<<<gq, 256>>>(v, Wv, vp, BSROWS, DE, DE);

    prep_ropesplit<<<(BSROWS * 512) / 256, 256>>>(qp, kp, rope_t, qh, ql, kh, kl);
    prep_vt<<<dim3(S_ / 64, NH, B_), 256>>>(vp, vth, vtl);

    attn_tc<<<dim3(S_ / 128, NH, B_), 256, ATTN_SMEM>>>(qh, ql, kh, kl, vth, vtl, at);

    gemm_mma<<<gq, 256>>>(at, Wo, out, BSROWS, DE, DE);
}

// round 12
// speedup vs baseline: 3.6484x; 1.2383x over previous
#include <cuda_runtime.h>
#include <cuda_bf16.h>
#include <math.h>
#include <stdint.h>

#define B_    4
#define S_    2048
#define DE    1024
#define NH    16
#define DH    64
#define BSROWS (B_ * S_)   // 8192

// fp32 scratch
__device__ float g_qp[(size_t)BSROWS * DE];
__device__ float g_kp[(size_t)BSROWS * DE];
__device__ float g_vp[(size_t)BSROWS * DE];
__device__ float g_at[(size_t)BSROWS * DE];
__device__ float2 g_rope[(size_t)S_ * 32];
// split-bf16 attention operands (hi/lo); vt is [b][h][d][s]
__device__ __nv_bfloat16 g_qh[(size_t)BSROWS * DE];
__device__ __nv_bfloat16 g_ql[(size_t)BSROWS * DE];
__device__ __nv_bfloat16 g_kh[(size_t)BSROWS * DE];
__device__ __nv_bfloat16 g_kl[(size_t)BSROWS * DE];
__device__ __nv_bfloat16 g_vth[(size_t)BSROWS * DE];
__device__ __nv_bfloat16 g_vtl[(size_t)BSROWS * DE];
// split-bf16 GEMM operand staging (reused per GEMM)
__device__ __nv_bfloat16 g_ah[(size_t)BSROWS * 2 * DE];
__device__ __nv_bfloat16 g_al[(size_t)BSROWS * 2 * DE];
__device__ __nv_bfloat16 g_wh[(size_t)DE * 2 * DE];
__device__ __nv_bfloat16 g_wl[(size_t)DE * 2 * DE];

// ===========================================================================
// Helpers
// ===========================================================================
__device__ __forceinline__ uint32_t smem_u32(const void* p) {
    uint32_t a;
    asm("{ .reg .u64 t; cvta.to.shared.u64 t, %1; cvt.u32.u64 %0, t; }"
        : "=r"(a) : "l"(p));
    return a;
}
__device__ __forceinline__ void ldm4(uint32_t* r, uint32_t addr) {
    asm volatile("ldmatrix.sync.aligned.m8n8.x4.shared.b16 {%0,%1,%2,%3}, [%4];"
                 : "=r"(r[0]), "=r"(r[1]), "=r"(r[2]), "=r"(r[3]) : "r"(addr));
}
__device__ __forceinline__ void mma16816(float* d, const uint32_t* a, const uint32_t* b) {
    asm volatile(
        "mma.sync.aligned.m16n8k16.row.col.f32.bf16.bf16.f32 "
        "{%0,%1,%2,%3}, {%4,%5,%6,%7}, {%8,%9}, {%0,%1,%2,%3};"
        : "+f"(d[0]), "+f"(d[1]), "+f"(d[2]), "+f"(d[3])
        : "r"(a[0]), "r"(a[1]), "r"(a[2]), "r"(a[3]), "r"(b[0]), "r"(b[1]));
}
__device__ __forceinline__ uint32_t pk_bf2(float a, float b) {
    __nv_bfloat162 t = __floats2bfloat162_rn(a, b);
    return *reinterpret_cast<uint32_t*>(&t);
}
__device__ __forceinline__ void split2(float a, float b, uint32_t& hi, uint32_t& lo) {
    float ha = __bfloat162float(__float2bfloat16_rn(a));
    float hb = __bfloat162float(__float2bfloat16_rn(b));
    hi = pk_bf2(ha, hb);
    lo = pk_bf2(a - ha, b - hb);
}
__device__ __forceinline__ void cp16(uint32_t dst, const void* src) {
    asm volatile("cp.async.cg.shared.global [%0], [%1], 16;"
                 :: "r"(dst), "l"(src) : "memory");
}
#define CP_COMMIT() asm volatile("cp.async.commit_group;" ::: "memory")
#define CP_WAIT(N)  asm volatile("cp.async.wait_group %0;" :: "n"(N) : "memory")
// SW64-style swizzle for 64B rows (4x 16B segs): seg ^= (row>>1)&3
__device__ __forceinline__ uint32_t swz64(uint32_t off) {
    return off ^ ((off >> 3) & 0x30);
}

// ===========================================================================
// prep_split: fp32 -> (bf16 hi, bf16 lo), elementwise. n4 = n/4.
// ===========================================================================
__global__ __launch_bounds__(256) void prep_split(const float* __restrict__ s,
                                                  __nv_bfloat16* __restrict__ h,
                                                  __nv_bfloat16* __restrict__ l,
                                                  int n4) {
    int i = blockIdx.x * 256 + threadIdx.x;
    if (i >= n4) return;
    float4 v = ((const float4*)s)[i];
    uint32_t h0, l0, h1, l1;
    split2(v.x, v.y, h0, l0);
    split2(v.z, v.w, h1, l1);
    ((uint2*)h)[i] = make_uint2(h0, h1);
    ((uint2*)l)[i] = make_uint2(l0, l1);
}

// ===========================================================================
// Pure-bf16 split GEMM: C[M][N] = (Ah+Al)[M][K] @ (Bh+Bl)[N][K]^T (3-pass).
// 128x128x32 tiles, cp.async 3-stage ring, SW64 swizzle, 2 CTAs/SM.
// ===========================================================================
#define GSTAGE_B 32768                 // 4 operands * 128*32*2 B
#define GEMM_SMEM (3 * GSTAGE_B)       // 98304 B

__global__ __launch_bounds__(256, 2) void gemm_bf(
    const __nv_bfloat16* __restrict__ Ah, const __nv_bfloat16* __restrict__ Al,
    const __nv_bfloat16* __restrict__ Bh, const __nv_bfloat16* __restrict__ Bl,
    float* __restrict__ C, int M, int N, int K) {
    extern __shared__ __align__(16) char gsm[];
    const uint32_t smb = smem_u32(gsm);
    const int tid = threadIdx.x;
    const int wid = tid >> 5;
    const int lane = tid & 31;
    const int bm = blockIdx.y * 128;
    const int bn = blockIdx.x * 128;
    const int wm = (wid >> 1) * 32;
    const int wn = (wid & 1) * 64;
    const int nch = K / 32;

    float acc[2][8][4];
#pragma unroll
    for (int f = 0; f < 2; f++)
#pragma unroll
        for (int n = 0; n < 8; n++)
#pragma unroll
            for (int i = 0; i < 4; i++) acc[f][n][i] = 0.f;

    auto issue = [&](int c, int s) {
        const uint32_t base = smb + (uint32_t)s * GSTAGE_B;
#pragma unroll
        for (int j = 0; j < 2; j++) {
            int ch = tid + 256 * j;
            int r = ch >> 2, sg = ch & 3;
            uint32_t d = swz64((uint32_t)r * 64 + sg * 16);
            const size_t ao = (size_t)(bm + r) * K + c * 32 + sg * 8;
            const size_t bo = (size_t)(bn + r) * K + c * 32 + sg * 8;
            cp16(base + d, Ah + ao);
            cp16(base + 8192 + d, Al + ao);
            cp16(base + 16384 + d, Bh + bo);
            cp16(base + 24576 + d, Bl + bo);
        }
        CP_COMMIT();
    };

    issue(0, 0);
    if (nch > 1) issue(1, 1);

    const int a_row = lane & 15;
    const int a_k8 = (lane >> 4) << 3;
    const int b_row = (lane & 7) + ((lane & 16) ? 8 : 0);
    const int b_k8 = (lane & 8) ? 8 : 0;

    int st = 0;
    for (int c = 0; c < nch; c++) {
        if (c + 2 < nch) { CP_WAIT(1); } else { CP_WAIT(0); }
        __syncthreads();
        if (c + 2 < nch) {
            int ns = st + 2;
            if (ns >= 3) ns -= 3;
            issue(c + 2, ns);
        }

        const uint32_t kb = smb + (uint32_t)st * GSTAGE_B;
#pragma unroll
        for (int ks = 0; ks < 32; ks += 16) {
            uint32_t ah[2][4], al[2][4];
#pragma unroll
            for (int f = 0; f < 2; f++) {
                uint32_t off = swz64((uint32_t)(wm + f * 16 + a_row) * 64 +
                                     (uint32_t)(ks + a_k8) * 2);
                ldm4(ah[f], kb + off);
                ldm4(al[f], kb + 8192 + off);
            }
#pragma unroll
            for (int g = 0; g < 4; g++) {
                uint32_t off = swz64((uint32_t)(wn + g * 16 + b_row) * 64 +
                                     (uint32_t)(ks + b_k8) * 2);
                uint32_t th[4], tl[4];
                ldm4(th, kb + 16384 + off);
                ldm4(tl, kb + 24576 + off);
                uint32_t bh0[2] = {th[0], th[1]}, bh1[2] = {th[2], th[3]};
                uint32_t bl0[2] = {tl[0], tl[1]}, bl1[2] = {tl[2], tl[3]};
#pragma unroll
                for (int f = 0; f < 2; f++) {
                    mma16816(acc[f][2 * g], ah[f], bh0);
                    mma16816(acc[f][2 * g], ah[f], bl0);
                    mma16816(acc[f][2 * g], al[f], bh0);
                    mma16816(acc[f][2 * g + 1], ah[f], bh1);
                    mma16816(acc[f][2 * g + 1], ah[f], bl1);
                    mma16816(acc[f][2 * g + 1], al[f], bh1);
                }
            }
        }
        if (++st == 3) st = 0;
        // next iteration's __syncthreads protects this stage before reuse
    }

    const int erow = lane >> 2;
    const int ecol = (lane & 3) * 2;
#pragma unroll
    for (int f = 0; f < 2; f++) {
        const size_t r0 = (size_t)(bm + wm + f * 16 + erow);
#pragma unroll
        for (int n = 0; n < 8; n++) {
            const size_t cc = (size_t)(bn + wn + n * 8 + ecol);
            *(float2*)&C[r0 * N + cc] = make_float2(acc[f][n][0], acc[f][n][1]);
            *(float2*)&C[(r0 + 8) * N + cc] = make_float2(acc[f][n][2], acc[f][n][3]);
        }
    }
}

// ===========================================================================
// RoPE table. sincos(x, SIN, COS) — sin first!
// ===========================================================================
__global__ void rope_table_kernel(float2* __restrict__ t) {
    int i = blockIdx.x * blockDim.x + threadIdx.x;
    int p = i & 31;
    int s = i >> 5;
    double inv = exp(-(double)p * (log(10000.0) / 32.0));
    double a = (double)s * inv;
    double sd, cd;
    sincos(a, &sd, &cd);
    t[i] = make_float2((float)cd, (float)sd);
}

// ===========================================================================
// Prep: RoPE + split-bf16. Q pre-scaled by 1/32 (exact power of 2).
// ===========================================================================
__global__ __launch_bounds__(256) void prep_ropesplit(
    const float* __restrict__ qp, const float* __restrict__ kp,
    const float2* __restrict__ rope_t,
    __nv_bfloat16* __restrict__ qh, __nv_bfloat16* __restrict__ ql,
    __nv_bfloat16* __restrict__ kh, __nv_bfloat16* __restrict__ kl) {
    size_t i = (size_t)blockIdx.x * 256 + threadIdx.x;   // < BSROWS*512
    int j = (int)(i & 511);
    size_t row = i >> 9;
    int pos = (int)(row & (S_ - 1));
    int pairp = j & 31;
    size_t off = row * DE + 2 * j;
    float2 cs = rope_t[pos * 32 + pairp];

    float2 x = *(const float2*)&qp[off];
    float o1 = (x.x * cs.x - x.y * cs.y) * 0.03125f;
    float o2 = (x.x * cs.y + x.y * cs.x) * 0.03125f;
    uint32_t hi, lo;
    split2(o1, o2, hi, lo);
    *(uint32_t*)&qh[off] = hi;
    *(uint32_t*)&ql[off] = lo;

    x = *(const float2*)&kp[off];
    o1 = x.x * cs.x - x.y * cs.y;
    o2 = x.x * cs.y + x.y * cs.x;
    split2(o1, o2, hi, lo);
    *(uint32_t*)&kh[off] = hi;
    *(uint32_t*)&kl[off] = lo;
}

// ===========================================================================
// Prep: V -> transposed split-bf16  vt[b][h][d][s]
// ===========================================================================
__global__ __launch_bounds__(256) void prep_vt(const float* __restrict__ vp,
                                               __nv_bfloat16* __restrict__ vth,
                                               __nv_bfloat16* __restrict__ vtl) {
    __shared__ float sm[64][65];
    const int tid = threadIdx.x;
    const int st = blockIdx.x, h = blockIdx.y, b = blockIdx.z;

    for (int i = tid; i < 1024; i += 256) {
        int r = i >> 4;
        int f4 = (i & 15) * 4;
        float4 v = *(const float4*)&vp[(size_t)(b * S_ + st * 64 + r) * DE + h * DH + f4];
        sm[r][f4] = v.x; sm[r][f4 + 1] = v.y; sm[r][f4 + 2] = v.z; sm[r][f4 + 3] = v.w;
    }
    __syncthreads();

    const int d = tid >> 2;
    const int ks = (tid & 3) * 16;
    uint32_t hi[8], lo[8];
#pragma unroll
    for (int j = 0; j < 8; j++)
        split2(sm[ks + 2 * j][d], sm[ks + 2 * j + 1][d], hi[j], lo[j]);

    __nv_bfloat16* dh = vth + ((size_t)((b * NH + h) * DH + d)) * S_ + st * 64 + ks;
    __nv_bfloat16* dl = vtl + ((size_t)((b * NH + h) * DH + d)) * S_ + st * 64 + ks;
    *(uint4*)&dh[0] = make_uint4(hi[0], hi[1], hi[2], hi[3]);
    *(uint4*)&dh[8] = make_uint4(hi[4], hi[5], hi[6], hi[7]);
    *(uint4*)&dl[0] = make_uint4(lo[0], lo[1], lo[2], lo[3]);
    *(uint4*)&dl[8] = make_uint4(lo[4], lo[5], lo[6], lo[7]);
}

// ===========================================================================
// Tensor-core causal flash attention (round-11, PASS — unchanged)
// ===========================================================================
#define AP 72
#define BUFE (256 * AP)
#define ATTN_SMEM (3 * BUFE * 2)

__global__ __launch_bounds__(256) void attn_tc(
    const __nv_bfloat16* __restrict__ qh, const __nv_bfloat16* __restrict__ ql,
    const __nv_bfloat16* __restrict__ kh, const __nv_bfloat16* __restrict__ kl,
    const __nv_bfloat16* __restrict__ vth, const __nv_bfloat16* __restrict__ vtl,
    float* __restrict__ outp) {
    extern __shared__ __align__(16) __nv_bfloat16 sm[];

    const int tid = threadIdx.x;
    const int w = tid >> 5;
    const int lane = tid & 31;
    const int b = blockIdx.z, h = blockIdx.y;
    const int q0 = blockIdx.x * 128;
    const uint32_t smb = smem_u32(sm);
    const int nkt = 2 * blockIdx.x + 2;

    const __nv_bfloat16* Kh = kh + (size_t)b * S_ * DE + h * DH;
    const __nv_bfloat16* Kl = kl + (size_t)b * S_ * DE + h * DH;
    const __nv_bfloat16* Vh = vth + (size_t)(b * NH + h) * DH * S_;
    const __nv_bfloat16* Vl = vtl + (size_t)(b * NH + h) * DH * S_;

    const int cr = tid >> 3;
    const int csg = tid & 7;

#pragma unroll
    for (int t0 = 0; t0 < 2; t0++) {
        const int k0 = t0 * 64;
        const uint32_t base = smb + (uint32_t)t0 * BUFE * 2;
#pragma unroll
        for (int j = 0; j < 2; j++) {
            int r = cr + 32 * j;
            uint32_t dof = ((uint32_t)r * AP + csg * 8) * 2;
            cp16(base + dof, Kh + (size_t)(k0 + r) * DE + csg * 8);
            cp16(base + 64 * AP * 2 + dof, Kl + (size_t)(k0 + r) * DE + csg * 8);
            cp16(base + 128 * AP * 2 + dof, Vh + (size_t)r * S_ + k0 + csg * 8);
            cp16(base + 192 * AP * 2 + dof, Vl + (size_t)r * S_ + k0 + csg * 8);
        }
        CP_COMMIT();
    }

    {
        __nv_bfloat16* qs = sm + 2 * BUFE;
        const __nv_bfloat16* sh = qh + (size_t)(b * S_ + q0) * DE + h * DH;
        const __nv_bfloat16* sl = ql + (size_t)(b * S_ + q0) * DE + h * DH;
#pragma unroll
        for (int j = 0; j < 4; j++) {
            int i = tid + 256 * j;
            int r = i >> 3, sg = i & 7;
            *(uint4*)&qs[r * AP + sg * 8] = *(const uint4*)&sh[(size_t)r * DE + sg * 8];
            *(uint4*)&qs[128 * AP + r * AP + sg * 8] =
                *(const uint4*)&sl[(size_t)r * DE + sg * 8];
        }
    }
    __syncthreads();

    uint32_t qfh[4][4], qfl[4][4];
    {
        const uint32_t qb = smb + 2 * BUFE * 2;
        const int arow = w * 16 + (lane & 15);
        const int ak8 = (lane >> 4) << 3;
#pragma unroll
        for (int kc = 0; kc < 4; kc++) {
            uint32_t off = (uint32_t)(arow * AP + kc * 16 + ak8) * 2;
            ldm4(qfh[kc], qb + off);
            ldm4(qfl[kc], qb + 128 * AP * 2 + off);
        }
    }
    __syncthreads();

    float oacc[8][4];
#pragma unroll
    for (int n = 0; n < 8; n++)
#pragma unroll
        for (int i = 0; i < 4; i++) oacc[n][i] = 0.f;
    float m0 = -1e30f, m1 = -1e30f, l0 = 0.f, l1 = 0.f;

    const int row0 = q0 + w * 16 + (lane >> 2);
    const int brow = (lane & 7) + ((lane & 16) ? 8 : 0);
    const int bk8 = (lane & 8) ? 8 : 0;

    int bufsel = 0;
    for (int kt = 0; kt < nkt; kt++) {
        const int k0 = kt * 64;
        if (kt + 2 < nkt) { CP_WAIT(1); } else { CP_WAIT(0); }
        __syncthreads();

        if (kt + 2 < nkt) {
            const int kn = k0 + 128;
            int nb = bufsel + 2;
            if (nb >= 3) nb -= 3;
            const uint32_t base = smb + (uint32_t)nb * BUFE * 2;
#pragma unroll
            for (int j = 0; j < 2; j++) {
                int r = cr + 32 * j;
                uint32_t dof = ((uint32_t)r * AP + csg * 8) * 2;
                cp16(base + dof, Kh + (size_t)(kn + r) * DE + csg * 8);
                cp16(base + 64 * AP * 2 + dof, Kl + (size_t)(kn + r) * DE + csg * 8);
                cp16(base + 128 * AP * 2 + dof, Vh + (size_t)r * S_ + kn + csg * 8);
                cp16(base + 192 * AP * 2 + dof, Vl + (size_t)r * S_ + kn + csg * 8);
            }
            CP_COMMIT();
        }

        const uint32_t kb = smb + (uint32_t)bufsel * BUFE * 2;

        float sacc[8][4];
#pragma unroll
        for (int n = 0; n < 8; n++)
#pragma unroll
            for (int i = 0; i < 4; i++) sacc[n][i] = 0.f;

#pragma unroll
        for (int kc = 0; kc < 4; kc++)
#pragma unroll
            for (int g = 0; g < 4; g++) {
                uint32_t off = (uint32_t)((g * 16 + brow) * AP + kc * 16 + bk8) * 2;
                uint32_t th[4], tl[4];
                ldm4(th, kb + off);
                ldm4(tl, kb + 64 * AP * 2 + off);
                uint32_t bh0[2] = {th[0], th[1]}, bh1[2] = {th[2], th[3]};
                uint32_t bl0[2] = {tl[0], tl[1]}, bl1[2] = {tl[2], tl[3]};
                mma16816(sacc[2 * g], qfh[kc], bh0);
                mma16816(sacc[2 * g], qfh[kc], bl0);
                mma16816(sacc[2 * g], qfl[kc], bh0);
                mma16816(sacc[2 * g + 1], qfh[kc], bh1);
                mma16816(sacc[2 * g + 1], qfh[kc], bl1);
                mma16816(sacc[2 * g + 1], qfl[kc], bh1);
            }

        if (kt >= nkt - 2) {
#pragma unroll
            for (int n = 0; n < 8; n++) {
                int col = k0 + n * 8 + (lane & 3) * 2;
                if (col > row0) sacc[n][0] = -1e30f;
                if (col + 1 > row0) sacc[n][1] = -1e30f;
                if (col > row0 + 8) sacc[n][2] = -1e30f;
                if (col + 1 > row0 + 8) sacc[n][3] = -1e30f;
            }
        }

        float mt0 = -1e30f, mt1 = -1e30f;
#pragma unroll
        for (int n = 0; n < 8; n++) {
            mt0 = fmaxf(mt0, fmaxf(sacc[n][0], sacc[n][1]));
            mt1 = fmaxf(mt1, fmaxf(sacc[n][2], sacc[n][3]));
        }
        mt0 = fmaxf(mt0, __shfl_xor_sync(0xffffffffu, mt0, 1));
        mt0 = fmaxf(mt0, __shfl_xor_sync(0xffffffffu, mt0, 2));
        mt1 = fmaxf(mt1, __shfl_xor_sync(0xffffffffu, mt1, 1));
        mt1 = fmaxf(mt1, __shfl_xor_sync(0xffffffffu, mt1, 2));

        float mn0 = fmaxf(m0, mt0), mn1 = fmaxf(m1, mt1);
        float a0 = __expf(m0 - mn0), a1 = __expf(m1 - mn1);
        m0 = mn0; m1 = mn1;

        float s0 = 0.f, s1 = 0.f;
#pragma unroll
        for (int n = 0; n < 8; n++) {
            sacc[n][0] = __expf(sacc[n][0] - mn0);
            sacc[n][1] = __expf(sacc[n][1] - mn0);
            sacc[n][2] = __expf(sacc[n][2] - mn1);
            sacc[n][3] = __expf(sacc[n][3] - mn1);
            s0 += sacc[n][0] + sacc[n][1];
            s1 += sacc[n][2] + sacc[n][3];
        }
        s0 += __shfl_xor_sync(0xffffffffu, s0, 1);
        s0 += __shfl_xor_sync(0xffffffffu, s0, 2);
        s1 += __shfl_xor_sync(0xffffffffu, s1, 1);
        s1 += __shfl_xor_sync(0xffffffffu, s1, 2);
        l0 = l0 * a0 + s0;
        l1 = l1 * a1 + s1;
#pragma unroll
        for (int n = 0; n < 8; n++) {
            oacc[n][0] *= a0; oacc[n][1] *= a0;
            oacc[n][2] *= a1; oacc[n][3] *= a1;
        }

#pragma unroll
        for (int kc = 0; kc < 4; kc++) {
            uint32_t pah[4], pal[4];
            split2(sacc[2 * kc][0], sacc[2 * kc][1], pah[0], pal[0]);
            split2(sacc[2 * kc][2], sacc[2 * kc][3], pah[1], pal[1]);
            split2(sacc[2 * kc + 1][0], sacc[2 * kc + 1][1], pah[2], pal[2]);
            split2(sacc[2 * kc + 1][2], sacc[2 * kc + 1][3], pah[3], pal[3]);
#pragma unroll
            for (int g = 0; g < 4; g++) {
                uint32_t off = (uint32_t)((g * 16 + brow) * AP + kc * 16 + bk8) * 2;
                uint32_t th[4], tl[4];
                ldm4(th, kb + 128 * AP * 2 + off);
                ldm4(tl, kb + 192 * AP * 2 + off);
                uint32_t bh0[2] = {th[0], th[1]}, bh1[2] = {th[2], th[3]};
                uint32_t bl0[2] = {tl[0], tl[1]}, bl1[2] = {tl[2], tl[3]};
                mma16816(oacc[2 * g], pah, bh0);
                mma16816(oacc[2 * g], pah, bl0);
                mma16816(oacc[2 * g], pal, bh0);
                mma16816(oacc[2 * g + 1], pah, bh1);
                mma16816(oacc[2 * g + 1], pah, bl1);
                mma16816(oacc[2 * g + 1], pal, bh1);
            }
        }

        if (++bufsel == 3) bufsel = 0;
    }

    const float inv0 = 1.0f / l0, inv1 = 1.0f / l1;
    const size_t gr0 = (size_t)(b * S_ + row0);
#pragma unroll
    for (int n = 0; n < 8; n++) {
        const size_t cc = (size_t)(h * DH + n * 8 + (lane & 3) * 2);
        *(float2*)&outp[gr0 * DE + cc] = make_float2(oacc[n][0] * inv0, oacc[n][1] * inv0);
        *(float2*)&outp[(gr0 + 8) * DE + cc] = make_float2(oacc[n][2] * inv1, oacc[n][3] * inv1);
    }
}

// ===========================================================================
extern "C" void kernel_launch(void* const* d_in, const int* in_sizes, int n_in,
                              void* d_out, int out_size) {
    const float* q  = (const float*)d_in[0];
    const float* k  = (const float*)d_in[1];
    const float* v  = (const float*)d_in[2];
    const float* Wq = (const float*)d_in[3];
    const float* Wk = (const float*)d_in[4];
    const float* Wv = (const float*)d_in[5];
    const float* Wo = (const float*)d_in[6];
    float* out = (float*)d_out;

    float *qp, *kp, *vp, *at;
    float2* rope_t;
    __nv_bfloat16 *qh, *ql, *kh, *kl, *vth, *vtl, *ah, *al, *wh, *wl;
    cudaGetSymbolAddress((void**)&qp, g_qp);
    cudaGetSymbolAddress((void**)&kp, g_kp);
    cudaGetSymbolAddress((void**)&vp, g_vp);
    cudaGetSymbolAddress((void**)&at, g_at);
    cudaGetSymbolAddress((void**)&rope_t, g_rope);
    cudaGetSymbolAddress((void**)&qh, g_qh);
    cudaGetSymbolAddress((void**)&ql, g_ql);
    cudaGetSymbolAddress((void**)&kh, g_kh);
    cudaGetSymbolAddress((void**)&kl, g_kl);
    cudaGetSymbolAddress((void**)&vth, g_vth);
    cudaGetSymbolAddress((void**)&vtl, g_vtl);
    cudaGetSymbolAddress((void**)&ah, g_ah);
    cudaGetSymbolAddress((void**)&al, g_al);
    cudaGetSymbolAddress((void**)&wh, g_wh);
    cudaGetSymbolAddress((void**)&wl, g_wl);

    cudaFuncSetAttribute(attn_tc, cudaFuncAttributeMaxDynamicSharedMemorySize,
                         ATTN_SMEM);
    cudaFuncSetAttribute(gemm_bf, cudaFuncAttributeMaxDynamicSharedMemorySize,
                         GEMM_SMEM);

    rope_table_kernel<<<(S_ * 32) / 256, 256>>>(rope_t);

    const int n_qk = BSROWS * 2 * DE;      // 16.7M
    const int n_v  = BSROWS * DE;          // 8.4M
    const int n_w2 = DE * 2 * DE;          // 2.1M
    const int n_w1 = DE * DE;              // 1.05M
    dim3 gq(DE / 128, BSROWS / 128);       // (8, 64)

    // Q projection
    prep_split<<<n_w2 / 1024, 256>>>(Wq, wh, wl, n_w2 / 4);
    prep_split<<<n_qk / 1024, 256>>>(q, ah, al, n_qk / 4);
    gemm_bf<<<gq, 256, GEMM_SMEM>>>(ah, al, wh, wl, qp, BSROWS, DE, 2 * DE);
    // K projection
    prep_split<<<n_w2 / 1024, 256>>>(Wk, wh, wl, n_w2 / 4);
    prep_split<<<n_qk / 1024, 256>>>(k, ah, al, n_qk / 4);
    gemm_bf<<<gq, 256, GEMM_SMEM>>>(ah, al, wh, wl, kp, BSROWS, DE, 2 * DE);
    // V projection
    prep_split<<<n_w1 / 1024, 256>>>(Wv, wh, wl, n_w1 / 4);
    prep_split<<<n_v / 1024, 256>>>(v, ah, al, n_v / 4);
    gemm_bf<<<gq, 256, GEMM_SMEM>>>(ah, al, wh, wl, vp, BSROWS, DE, DE);

    prep_ropesplit<<<(BSROWS * 512) / 256, 256>>>(qp, kp, rope_t, qh, ql, kh, kl);
    prep_vt<<<dim3(S_ / 64, NH, B_), 256>>>(vp, vth, vtl);

    attn_tc<<<dim3(S_ / 128, NH, B_), 256, ATTN_SMEM>>>(qh, ql, kh, kl, vth, vtl, at);

    // Output projection
    prep_split<<<n_w1 / 1024, 256>>>(Wo, wh, wl, n_w1 / 4);
    prep_split<<<n_v / 1024, 256>>>(at, ah, al, n_v / 4);
    gemm_bf<<<gq, 256, GEMM_SMEM>>>(ah, al, wh, wl, out, BSROWS, DE, DE);
}

// round 13
// speedup vs baseline: 5.7774x; 1.5835x over previous
#include <cuda_runtime.h>
#include <cuda_bf16.h>
#include <cuda_fp16.h>
#include <math.h>
#include <stdint.h>

#define B_    4
#define S_    2048
#define DE    1024
#define NH    16
#define DH    64
#define BSROWS (B_ * S_)   // 8192

// fp32 scratch
__device__ float g_qp[(size_t)BSROWS * DE];
__device__ float g_kp[(size_t)BSROWS * DE];
__device__ float g_vp[(size_t)BSROWS * DE];
__device__ float g_at[(size_t)BSROWS * DE];
__device__ float2 g_rope[(size_t)S_ * 32];
// split-bf16 attention operands (hi/lo); vt is [b][h][d][s]
__device__ __nv_bfloat16 g_qh[(size_t)BSROWS * DE];
__device__ __nv_bfloat16 g_ql[(size_t)BSROWS * DE];
__device__ __nv_bfloat16 g_kh[(size_t)BSROWS * DE];
__device__ __nv_bfloat16 g_kl[(size_t)BSROWS * DE];
__device__ __nv_bfloat16 g_vth[(size_t)BSROWS * DE];
__device__ __nv_bfloat16 g_vtl[(size_t)BSROWS * DE];
// fp16 GEMM operand staging (reused per GEMM)
__device__ __half g_af[(size_t)BSROWS * 2 * DE];
__device__ __half g_wf[(size_t)DE * 2 * DE];

// ===========================================================================
// Helpers
// ===========================================================================
__device__ __forceinline__ uint32_t smem_u32(const void* p) {
    uint32_t a;
    asm("{ .reg .u64 t; cvta.to.shared.u64 t, %1; cvt.u32.u64 %0, t; }"
        : "=r"(a) : "l"(p));
    return a;
}
__device__ __forceinline__ void ldm4(uint32_t* r, uint32_t addr) {
    asm volatile("ldmatrix.sync.aligned.m8n8.x4.shared.b16 {%0,%1,%2,%3}, [%4];"
                 : "=r"(r[0]), "=r"(r[1]), "=r"(r[2]), "=r"(r[3]) : "r"(addr));
}
__device__ __forceinline__ void mma16816(float* d, const uint32_t* a, const uint32_t* b) {
    asm volatile(
        "mma.sync.aligned.m16n8k16.row.col.f32.bf16.bf16.f32 "
        "{%0,%1,%2,%3}, {%4,%5,%6,%7}, {%8,%9}, {%0,%1,%2,%3};"
        : "+f"(d[0]), "+f"(d[1]), "+f"(d[2]), "+f"(d[3])
        : "r"(a[0]), "r"(a[1]), "r"(a[2]), "r"(a[3]), "r"(b[0]), "r"(b[1]));
}
__device__ __forceinline__ void mma16816h(float* d, const uint32_t* a, const uint32_t* b) {
    asm volatile(
        "mma.sync.aligned.m16n8k16.row.col.f32.f16.f16.f32 "
        "{%0,%1,%2,%3}, {%4,%5,%6,%7}, {%8,%9}, {%0,%1,%2,%3};"
        : "+f"(d[0]), "+f"(d[1]), "+f"(d[2]), "+f"(d[3])
        : "r"(a[0]), "r"(a[1]), "r"(a[2]), "r"(a[3]), "r"(b[0]), "r"(b[1]));
}
__device__ __forceinline__ uint32_t pk_bf2(float a, float b) {
    __nv_bfloat162 t = __floats2bfloat162_rn(a, b);
    return *reinterpret_cast<uint32_t*>(&t);
}
__device__ __forceinline__ void split2(float a, float b, uint32_t& hi, uint32_t& lo) {
    float ha = __bfloat162float(__float2bfloat16_rn(a));
    float hb = __bfloat162float(__float2bfloat16_rn(b));
    hi = pk_bf2(ha, hb);
    lo = pk_bf2(a - ha, b - hb);
}
__device__ __forceinline__ void cp16(uint32_t dst, const void* src) {
    asm volatile("cp.async.cg.shared.global [%0], [%1], 16;"
                 :: "r"(dst), "l"(src) : "memory");
}
#define CP_COMMIT() asm volatile("cp.async.commit_group;" ::: "memory")
#define CP_WAIT(N)  asm volatile("cp.async.wait_group %0;" :: "n"(N) : "memory")
__device__ __forceinline__ uint32_t swz64(uint32_t off) {
    return off ^ ((off >> 3) & 0x30);
}

// ===========================================================================
// prep_h: fp32 -> fp16, elementwise, vectorized. n4 = n/4.
// ===========================================================================
__global__ __launch_bounds__(256) void prep_h(const float* __restrict__ s,
                                              __half* __restrict__ d, int n4) {
    int i = blockIdx.x * 256 + threadIdx.x;
    if (i >= n4) return;
    float4 v = ((const float4*)s)[i];
    __half2 a = __floats2half2_rn(v.x, v.y);
    __half2 b = __floats2half2_rn(v.z, v.w);
    ((uint2*)d)[i] = make_uint2(*(uint32_t*)&a, *(uint32_t*)&b);
}

// ===========================================================================
// Single-pass fp16 GEMM: C[M][N] = A[M][K] @ B[N][K]^T, fp32 accumulate.
// 128x128x32 tiles, cp.async 3-stage ring, SW64 swizzle.
// ===========================================================================
#define HSTAGE_B 16384                 // 2 operands * 128*32*2 B
#define GEMMH_SMEM (3 * HSTAGE_B)      // 49152 B

__global__ __launch_bounds__(256, 2) void gemm_hf(
    const __half* __restrict__ A, const __half* __restrict__ B,
    float* __restrict__ C, int M, int N, int K) {
    extern __shared__ __align__(16) char gsm[];
    const uint32_t smb = smem_u32(gsm);
    const int tid = threadIdx.x;
    const int wid = tid >> 5;
    const int lane = tid & 31;
    const int bm = blockIdx.y * 128;
    const int bn = blockIdx.x * 128;
    const int wm = (wid >> 1) * 32;
    const int wn = (wid & 1) * 64;
    const int nch = K / 32;

    float acc[2][8][4];
#pragma unroll
    for (int f = 0; f < 2; f++)
#pragma unroll
        for (int n = 0; n < 8; n++)
#pragma unroll
            for (int i = 0; i < 4; i++) acc[f][n][i] = 0.f;

    auto issue = [&](int c, int s) {
        const uint32_t base = smb + (uint32_t)s * HSTAGE_B;
#pragma unroll
        for (int j = 0; j < 2; j++) {
            int ch = tid + 256 * j;              // 0..511
            int r = ch >> 2, sg = ch & 3;
            uint32_t d = swz64((uint32_t)r * 64 + sg * 16);
            cp16(base + d, A + (size_t)(bm + r) * K + c * 32 + sg * 8);
            cp16(base + 8192 + d, B + (size_t)(bn + r) * K + c * 32 + sg * 8);
        }
        CP_COMMIT();
    };

    issue(0, 0);
    if (nch > 1) issue(1, 1);

    const int a_row = lane & 15;
    const int a_k8 = (lane >> 4) << 3;
    const int b_row = (lane & 7) + ((lane & 16) ? 8 : 0);
    const int b_k8 = (lane & 8) ? 8 : 0;

    int st = 0;
    for (int c = 0; c < nch; c++) {
        if (c + 2 < nch) { CP_WAIT(1); } else { CP_WAIT(0); }
        __syncthreads();
        if (c + 2 < nch) {
            int ns = st + 2;
            if (ns >= 3) ns -= 3;
            issue(c + 2, ns);
        }

        const uint32_t kb = smb + (uint32_t)st * HSTAGE_B;
#pragma unroll
        for (int ks = 0; ks < 32; ks += 16) {
            uint32_t af[2][4];
#pragma unroll
            for (int f = 0; f < 2; f++) {
                uint32_t off = swz64((uint32_t)(wm + f * 16 + a_row) * 64 +
                                     (uint32_t)(ks + a_k8) * 2);
                ldm4(af[f], kb + off);
            }
#pragma unroll
            for (int g = 0; g < 4; g++) {
                uint32_t off = swz64((uint32_t)(wn + g * 16 + b_row) * 64 +
                                     (uint32_t)(ks + b_k8) * 2);
                uint32_t t[4];
                ldm4(t, kb + 8192 + off);
                uint32_t b0[2] = {t[0], t[1]}, b1[2] = {t[2], t[3]};
#pragma unroll
                for (int f = 0; f < 2; f++) {
                    mma16816h(acc[f][2 * g], af[f], b0);
                    mma16816h(acc[f][2 * g + 1], af[f], b1);
                }
            }
        }
        if (++st == 3) st = 0;
    }

    const int erow = lane >> 2;
    const int ecol = (lane & 3) * 2;
#pragma unroll
    for (int f = 0; f < 2; f++) {
        const size_t r0 = (size_t)(bm + wm + f * 16 + erow);
#pragma unroll
        for (int n = 0; n < 8; n++) {
            const size_t cc = (size_t)(bn + wn + n * 8 + ecol);
            *(float2*)&C[r0 * N + cc] = make_float2(acc[f][n][0], acc[f][n][1]);
            *(float2*)&C[(r0 + 8) * N + cc] = make_float2(acc[f][n][2], acc[f][n][3]);
        }
    }
}

// ===========================================================================
// RoPE table. sincos(x, SIN, COS) — sin first!
// ===========================================================================
__global__ void rope_table_kernel(float2* __restrict__ t) {
    int i = blockIdx.x * blockDim.x + threadIdx.x;
    int p = i & 31;
    int s = i >> 5;
    double inv = exp(-(double)p * (log(10000.0) / 32.0));
    double a = (double)s * inv;
    double sd, cd;
    sincos(a, &sd, &cd);
    t[i] = make_float2((float)cd, (float)sd);
}

// ===========================================================================
// Prep: RoPE + split-bf16. Q pre-scaled by 1/32.
// ===========================================================================
__global__ __launch_bounds__(256) void prep_ropesplit(
    const float* __restrict__ qp, const float* __restrict__ kp,
    const float2* __restrict__ rope_t,
    __nv_bfloat16* __restrict__ qh, __nv_bfloat16* __restrict__ ql,
    __nv_bfloat16* __restrict__ kh, __nv_bfloat16* __restrict__ kl) {
    size_t i = (size_t)blockIdx.x * 256 + threadIdx.x;   // < BSROWS*512
    int j = (int)(i & 511);
    size_t row = i >> 9;
    int pos = (int)(row & (S_ - 1));
    int pairp = j & 31;
    size_t off = row * DE + 2 * j;
    float2 cs = rope_t[pos * 32 + pairp];

    float2 x = *(const float2*)&qp[off];
    float o1 = (x.x * cs.x - x.y * cs.y) * 0.03125f;
    float o2 = (x.x * cs.y + x.y * cs.x) * 0.03125f;
    uint32_t hi, lo;
    split2(o1, o2, hi, lo);
    *(uint32_t*)&qh[off] = hi;
    *(uint32_t*)&ql[off] = lo;

    x = *(const float2*)&kp[off];
    o1 = x.x * cs.x - x.y * cs.y;
    o2 = x.x * cs.y + x.y * cs.x;
    split2(o1, o2, hi, lo);
    *(uint32_t*)&kh[off] = hi;
    *(uint32_t*)&kl[off] = lo;
}

// ===========================================================================
// Prep: V -> transposed split-bf16  vt[b][h][d][s]
// ===========================================================================
__global__ __launch_bounds__(256) void prep_vt(const float* __restrict__ vp,
                                               __nv_bfloat16* __restrict__ vth,
                                               __nv_bfloat16* __restrict__ vtl) {
    __shared__ float sm[64][65];
    const int tid = threadIdx.x;
    const int st = blockIdx.x, h = blockIdx.y, b = blockIdx.z;

    for (int i = tid; i < 1024; i += 256) {
        int r = i >> 4;
        int f4 = (i & 15) * 4;
        float4 v = *(const float4*)&vp[(size_t)(b * S_ + st * 64 + r) * DE + h * DH + f4];
        sm[r][f4] = v.x; sm[r][f4 + 1] = v.y; sm[r][f4 + 2] = v.z; sm[r][f4 + 3] = v.w;
    }
    __syncthreads();

    const int d = tid >> 2;
    const int ks = (tid & 3) * 16;
    uint32_t hi[8], lo[8];
#pragma unroll
    for (int j = 0; j < 8; j++)
        split2(sm[ks + 2 * j][d], sm[ks + 2 * j + 1][d], hi[j], lo[j]);

    __nv_bfloat16* dh = vth + ((size_t)((b * NH + h) * DH + d)) * S_ + st * 64 + ks;
    __nv_bfloat16* dl = vtl + ((size_t)((b * NH + h) * DH + d)) * S_ + st * 64 + ks;
    *(uint4*)&dh[0] = make_uint4(hi[0], hi[1], hi[2], hi[3]);
    *(uint4*)&dh[8] = make_uint4(hi[4], hi[5], hi[6], hi[7]);
    *(uint4*)&dl[0] = make_uint4(lo[0], lo[1], lo[2], lo[3]);
    *(uint4*)&dl[8] = make_uint4(lo[4], lo[5], lo[6], lo[7]);
}

// ===========================================================================
// Tensor-core causal flash attention (round-11/12, PASS — unchanged)
// ===========================================================================
#define AP 72
#define BUFE (256 * AP)
#define ATTN_SMEM (3 * BUFE * 2)

__global__ __launch_bounds__(256) void attn_tc(
    const __nv_bfloat16* __restrict__ qh, const __nv_bfloat16* __restrict__ ql,
    const __nv_bfloat16* __restrict__ kh, const __nv_bfloat16* __restrict__ kl,
    const __nv_bfloat16* __restrict__ vth, const __nv_bfloat16* __restrict__ vtl,
    float* __restrict__ outp) {
    extern __shared__ __align__(16) __nv_bfloat16 sm[];

    const int tid = threadIdx.x;
    const int w = tid >> 5;
    const int lane = tid & 31;
    const int b = blockIdx.z, h = blockIdx.y;
    const int q0 = blockIdx.x * 128;
    const uint32_t smb = smem_u32(sm);
    const int nkt = 2 * blockIdx.x + 2;

    const __nv_bfloat16* Kh = kh + (size_t)b * S_ * DE + h * DH;
    const __nv_bfloat16* Kl = kl + (size_t)b * S_ * DE + h * DH;
    const __nv_bfloat16* Vh = vth + (size_t)(b * NH + h) * DH * S_;
    const __nv_bfloat16* Vl = vtl + (size_t)(b * NH + h) * DH * S_;

    const int cr = tid >> 3;
    const int csg = tid & 7;

#pragma unroll
    for (int t0 = 0; t0 < 2; t0++) {
        const int k0 = t0 * 64;
        const uint32_t base = smb + (uint32_t)t0 * BUFE * 2;
#pragma unroll
        for (int j = 0; j < 2; j++) {
            int r = cr + 32 * j;
            uint32_t dof = ((uint32_t)r * AP + csg * 8) * 2;
            cp16(base + dof, Kh + (size_t)(k0 + r) * DE + csg * 8);
            cp16(base + 64 * AP * 2 + dof, Kl + (size_t)(k0 + r) * DE + csg * 8);
            cp16(base + 128 * AP * 2 + dof, Vh + (size_t)r * S_ + k0 + csg * 8);
            cp16(base + 192 * AP * 2 + dof, Vl + (size_t)r * S_ + k0 + csg * 8);
        }
        CP_COMMIT();
    }

    {
        __nv_bfloat16* qs = sm + 2 * BUFE;
        const __nv_bfloat16* sh = qh + (size_t)(b * S_ + q0) * DE + h * DH;
        const __nv_bfloat16* sl = ql + (size_t)(b * S_ + q0) * DE + h * DH;
#pragma unroll
        for (int j = 0; j < 4; j++) {
            int i = tid + 256 * j;
            int r = i >> 3, sg = i & 7;
            *(uint4*)&qs[r * AP + sg * 8] = *(const uint4*)&sh[(size_t)r * DE + sg * 8];
            *(uint4*)&qs[128 * AP + r * AP + sg * 8] =
                *(const uint4*)&sl[(size_t)r * DE + sg * 8];
        }
    }
    __syncthreads();

    uint32_t qfh[4][4], qfl[4][4];
    {
        const uint32_t qb = smb + 2 * BUFE * 2;
        const int arow = w * 16 + (lane & 15);
        const int ak8 = (lane >> 4) << 3;
#pragma unroll
        for (int kc = 0; kc < 4; kc++) {
            uint32_t off = (uint32_t)(arow * AP + kc * 16 + ak8) * 2;
            ldm4(qfh[kc], qb + off);
            ldm4(qfl[kc], qb + 128 * AP * 2 + off);
        }
    }
    __syncthreads();

    float oacc[8][4];
#pragma unroll
    for (int n = 0; n < 8; n++)
#pragma unroll
        for (int i = 0; i < 4; i++) oacc[n][i] = 0.f;
    float m0 = -1e30f, m1 = -1e30f, l0 = 0.f, l1 = 0.f;

    const int row0 = q0 + w * 16 + (lane >> 2);
    const int brow = (lane & 7) + ((lane & 16) ? 8 : 0);
    const int bk8 = (lane & 8) ? 8 : 0;

    int bufsel = 0;
    for (int kt = 0; kt < nkt; kt++) {
        const int k0 = kt * 64;
        if (kt + 2 < nkt) { CP_WAIT(1); } else { CP_WAIT(0); }
        __syncthreads();

        if (kt + 2 < nkt) {
            const int kn = k0 + 128;
            int nb = bufsel + 2;
            if (nb >= 3) nb -= 3;
            const uint32_t base = smb + (uint32_t)nb * BUFE * 2;
#pragma unroll
            for (int j = 0; j < 2; j++) {
                int r = cr + 32 * j;
                uint32_t dof = ((uint32_t)r * AP + csg * 8) * 2;
                cp16(base + dof, Kh + (size_t)(kn + r) * DE + csg * 8);
                cp16(base + 64 * AP * 2 + dof, Kl + (size_t)(kn + r) * DE + csg * 8);
                cp16(base + 128 * AP * 2 + dof, Vh + (size_t)r * S_ + kn + csg * 8);
                cp16(base + 192 * AP * 2 + dof, Vl + (size_t)r * S_ + kn + csg * 8);
            }
            CP_COMMIT();
        }

        const uint32_t kb = smb + (uint32_t)bufsel * BUFE * 2;

        float sacc[8][4];
#pragma unroll
        for (int n = 0; n < 8; n++)
#pragma unroll
            for (int i = 0; i < 4; i++) sacc[n][i] = 0.f;

#pragma unroll
        for (int kc = 0; kc < 4; kc++)
#pragma unroll
            for (int g = 0; g < 4; g++) {
                uint32_t off = (uint32_t)((g * 16 + brow) * AP + kc * 16 + bk8) * 2;
                uint32_t th[4], tl[4];
                ldm4(th, kb + off);
                ldm4(tl, kb + 64 * AP * 2 + off);
                uint32_t bh0[2] = {th[0], th[1]}, bh1[2] = {th[2], th[3]};
                uint32_t bl0[2] = {tl[0], tl[1]}, bl1[2] = {tl[2], tl[3]};
                mma16816(sacc[2 * g], qfh[kc], bh0);
                mma16816(sacc[2 * g], qfh[kc], bl0);
                mma16816(sacc[2 * g], qfl[kc], bh0);
                mma16816(sacc[2 * g + 1], qfh[kc], bh1);
                mma16816(sacc[2 * g + 1], qfh[kc], bl1);
                mma16816(sacc[2 * g + 1], qfl[kc], bh1);
            }

        if (kt >= nkt - 2) {
#pragma unroll
            for (int n = 0; n < 8; n++) {
                int col = k0 + n * 8 + (lane & 3) * 2;
                if (col > row0) sacc[n][0] = -1e30f;
                if (col + 1 > row0) sacc[n][1] = -1e30f;
                if (col > row0 + 8) sacc[n][2] = -1e30f;
                if (col + 1 > row0 + 8) sacc[n][3] = -1e30f;
            }
        }

        float mt0 = -1e30f, mt1 = -1e30f;
#pragma unroll
        for (int n = 0; n < 8; n++) {
            mt0 = fmaxf(mt0, fmaxf(sacc[n][0], sacc[n][1]));
            mt1 = fmaxf(mt1, fmaxf(sacc[n][2], sacc[n][3]));
        }
        mt0 = fmaxf(mt0, __shfl_xor_sync(0xffffffffu, mt0, 1));
        mt0 = fmaxf(mt0, __shfl_xor_sync(0xffffffffu, mt0, 2));
        mt1 = fmaxf(mt1, __shfl_xor_sync(0xffffffffu, mt1, 1));
        mt1 = fmaxf(mt1, __shfl_xor_sync(0xffffffffu, mt1, 2));

        float mn0 = fmaxf(m0, mt0), mn1 = fmaxf(m1, mt1);
        float a0 = __expf(m0 - mn0), a1 = __expf(m1 - mn1);
        m0 = mn0; m1 = mn1;

        float s0 = 0.f, s1 = 0.f;
#pragma unroll
        for (int n = 0; n < 8; n++) {
            sacc[n][0] = __expf(sacc[n][0] - mn0);
            sacc[n][1] = __expf(sacc[n][1] - mn0);
            sacc[n][2] = __expf(sacc[n][2] - mn1);
            sacc[n][3] = __expf(sacc[n][3] - mn1);
            s0 += sacc[n][0] + sacc[n][1];
            s1 += sacc[n][2] + sacc[n][3];
        }
        s0 += __shfl_xor_sync(0xffffffffu, s0, 1);
        s0 += __shfl_xor_sync(0xffffffffu, s0, 2);
        s1 += __shfl_xor_sync(0xffffffffu, s1, 1);
        s1 += __shfl_xor_sync(0xffffffffu, s1, 2);
        l0 = l0 * a0 + s0;
        l1 = l1 * a1 + s1;
#pragma unroll
        for (int n = 0; n < 8; n++) {
            oacc[n][0] *= a0; oacc[n][1] *= a0;
            oacc[n][2] *= a1; oacc[n][3] *= a1;
        }

#pragma unroll
        for (int kc = 0; kc < 4; kc++) {
            uint32_t pah[4], pal[4];
            split2(sacc[2 * kc][0], sacc[2 * kc][1], pah[0], pal[0]);
            split2(sacc[2 * kc][2], sacc[2 * kc][3], pah[1], pal[1]);
            split2(sacc[2 * kc + 1][0], sacc[2 * kc + 1][1], pah[2], pal[2]);
            split2(sacc[2 * kc + 1][2], sacc[2 * kc + 1][3], pah[3], pal[3]);
#pragma unroll
            for (int g = 0; g < 4; g++) {
                uint32_t off = (uint32_t)((g * 16 + brow) * AP + kc * 16 + bk8) * 2;
                uint32_t th[4], tl[4];
                ldm4(th, kb + 128 * AP * 2 + off);
                ldm4(tl, kb + 192 * AP * 2 + off);
                uint32_t bh0[2] = {th[0], th[1]}, bh1[2] = {th[2], th[3]};
                uint32_t bl0[2] = {tl[0], tl[1]}, bl1[2] = {tl[2], tl[3]};
                mma16816(oacc[2 * g], pah, bh0);
                mma16816(oacc[2 * g], pah, bl0);
                mma16816(oacc[2 * g], pal, bh0);
                mma16816(oacc[2 * g + 1], pah, bh1);
                mma16816(oacc[2 * g + 1], pah, bl1);
                mma16816(oacc[2 * g + 1], pal, bh1);
            }
        }

        if (++bufsel == 3) bufsel = 0;
    }

    const float inv0 = 1.0f / l0, inv1 = 1.0f / l1;
    const size_t gr0 = (size_t)(b * S_ + row0);
#pragma unroll
    for (int n = 0; n < 8; n++) {
        const size_t cc = (size_t)(h * DH + n * 8 + (lane & 3) * 2);
        *(float2*)&outp[gr0 * DE + cc] = make_float2(oacc[n][0] * inv0, oacc[n][1] * inv0);
        *(float2*)&outp[(gr0 + 8) * DE + cc] = make_float2(oacc[n][2] * inv1, oacc[n][3] * inv1);
    }
}

// ===========================================================================
extern "C" void kernel_launch(void* const* d_in, const int* in_sizes, int n_in,
                              void* d_out, int out_size) {
    const float* q  = (const float*)d_in[0];
    const float* k  = (const float*)d_in[1];
    const float* v  = (const float*)d_in[2];
    const float* Wq = (const float*)d_in[3];
    const float* Wk = (const float*)d_in[4];
    const float* Wv = (const float*)d_in[5];
    const float* Wo = (const float*)d_in[6];
    float* out = (float*)d_out;

    float *qp, *kp, *vp, *at;
    float2* rope_t;
    __nv_bfloat16 *qh, *ql, *kh, *kl, *vth, *vtl;
    __half *af, *wf;
    cudaGetSymbolAddress((void**)&qp, g_qp);
    cudaGetSymbolAddress((void**)&kp, g_kp);
    cudaGetSymbolAddress((void**)&vp, g_vp);
    cudaGetSymbolAddress((void**)&at, g_at);
    cudaGetSymbolAddress((void**)&rope_t, g_rope);
    cudaGetSymbolAddress((void**)&qh, g_qh);
    cudaGetSymbolAddress((void**)&ql, g_ql);
    cudaGetSymbolAddress((void**)&kh, g_kh);
    cudaGetSymbolAddress((void**)&kl, g_kl);
    cudaGetSymbolAddress((void**)&vth, g_vth);
    cudaGetSymbolAddress((void**)&vtl, g_vtl);
    cudaGetSymbolAddress((void**)&af, g_af);
    cudaGetSymbolAddress((void**)&wf, g_wf);

    cudaFuncSetAttribute(attn_tc, cudaFuncAttributeMaxDynamicSharedMemorySize,
                         ATTN_SMEM);
    cudaFuncSetAttribute(gemm_hf, cudaFuncAttributeMaxDynamicSharedMemorySize,
                         GEMMH_SMEM);

    rope_table_kernel<<<(S_ * 32) / 256, 256>>>(rope_t);

    const int n_qk = BSROWS * 2 * DE;
    const int n_v  = BSROWS * DE;
    const int n_w2 = DE * 2 * DE;
    const int n_w1 = DE * DE;
    dim3 gq(DE / 128, BSROWS / 128);       // (8, 64)

    // Q projection
    prep_h<<<n_w2 / 1024, 256>>>(Wq, wf, n_w2 / 4);
    prep_h<<<n_qk / 1024, 256>>>(q, af, n_qk / 4);
    gemm_hf<<<gq, 256, GEMMH_SMEM>>>(af, wf, qp, BSROWS, DE, 2 * DE);
    // K projection
    prep_h<<<n_w2 / 1024, 256>>>(Wk, wf, n_w2 / 4);
    prep_h<<<n_qk / 1024, 256>>>(k, af, n_qk / 4);
    gemm_hf<<<gq, 256, GEMMH_SMEM>>>(af, wf, kp, BSROWS, DE, 2 * DE);
    // V projection
    prep_h<<<n_w1 / 1024, 256>>>(Wv, wf, n_w1 / 4);
    prep_h<<<n_v / 1024, 256>>>(v, af, n_v / 4);
    gemm_hf<<<gq, 256, GEMMH_SMEM>>>(af, wf, vp, BSROWS, DE, DE);

    prep_ropesplit<<<(BSROWS * 512) / 256, 256>>>(qp, kp, rope_t, qh, ql, kh, kl);
    prep_vt<<<dim3(S_ / 64, NH, B_), 256>>>(vp, vth, vtl);

    attn_tc<<<dim3(S_ / 128, NH, B_), 256, ATTN_SMEM>>>(qh, ql, kh, kl, vth, vtl, at);

    // Output projection
    prep_h<<<n_w1 / 1024, 256>>>(Wo, wf, n_w1 / 4);
    prep_h<<<n_v / 1024, 256>>>(at, af, n_v / 4);
    gemm_hf<<<gq, 256, GEMMH_SMEM>>>(af, wf, out, BSROWS, DE, DE);
}

// round 14
// speedup vs baseline: 7.9145x; 1.3699x over previous
#include <cuda_runtime.h>
#include <cuda_fp16.h>
#include <math.h>
#include <stdint.h>

#define B_    4
#define S_    2048
#define DE    1024
#define NH    16
#define DH    64
#define BSROWS (B_ * S_)   // 8192

// fp32 scratch
__device__ float g_qp[(size_t)BSROWS * DE];
__device__ float g_kp[(size_t)BSROWS * DE];
__device__ float g_vp[(size_t)BSROWS * DE];
__device__ float2 g_rope[(size_t)S_ * 32];
// fp16 attention operands; vt is [b][h][d][s]
__device__ __half g_qf2[(size_t)BSROWS * DE];
__device__ __half g_kf2[(size_t)BSROWS * DE];
__device__ __half g_vt2[(size_t)BSROWS * DE];
// fp16 GEMM operand staging
__device__ __half g_af[(size_t)BSROWS * 2 * DE];
__device__ __half g_wf[(size_t)DE * 2 * DE];

// ===========================================================================
// Helpers
// ===========================================================================
__device__ __forceinline__ uint32_t smem_u32(const void* p) {
    uint32_t a;
    asm("{ .reg .u64 t; cvta.to.shared.u64 t, %1; cvt.u32.u64 %0, t; }"
        : "=r"(a) : "l"(p));
    return a;
}
__device__ __forceinline__ void ldm4(uint32_t* r, uint32_t addr) {
    asm volatile("ldmatrix.sync.aligned.m8n8.x4.shared.b16 {%0,%1,%2,%3}, [%4];"
                 : "=r"(r[0]), "=r"(r[1]), "=r"(r[2]), "=r"(r[3]) : "r"(addr));
}
__device__ __forceinline__ void mma16816h(float* d, const uint32_t* a, const uint32_t* b) {
    asm volatile(
        "mma.sync.aligned.m16n8k16.row.col.f32.f16.f16.f32 "
        "{%0,%1,%2,%3}, {%4,%5,%6,%7}, {%8,%9}, {%0,%1,%2,%3};"
        : "+f"(d[0]), "+f"(d[1]), "+f"(d[2]), "+f"(d[3])
        : "r"(a[0]), "r"(a[1]), "r"(a[2]), "r"(a[3]), "r"(b[0]), "r"(b[1]));
}
__device__ __forceinline__ uint32_t pk_h2(float a, float b) {
    __half2 t = __floats2half2_rn(a, b);
    return *reinterpret_cast<uint32_t*>(&t);
}
__device__ __forceinline__ void cp16(uint32_t dst, const void* src) {
    asm volatile("cp.async.cg.shared.global [%0], [%1], 16;"
                 :: "r"(dst), "l"(src) : "memory");
}
#define CP_COMMIT() asm volatile("cp.async.commit_group;" ::: "memory")
#define CP_WAIT(N)  asm volatile("cp.async.wait_group %0;" :: "n"(N) : "memory")
__device__ __forceinline__ uint32_t swz64(uint32_t off) {
    return off ^ ((off >> 3) & 0x30);
}

// ===========================================================================
// prep_h: fp32 -> fp16, elementwise. n4 = n/4.
// ===========================================================================
__global__ __launch_bounds__(256) void prep_h(const float* __restrict__ s,
                                              __half* __restrict__ d, int n4) {
    int i = blockIdx.x * 256 + threadIdx.x;
    if (i >= n4) return;
    float4 v = ((const float4*)s)[i];
    ((uint2*)d)[i] = make_uint2(pk_h2(v.x, v.y), pk_h2(v.z, v.w));
}

// ===========================================================================
// Single-pass fp16 GEMM (round-13, PASS — unchanged)
// ===========================================================================
#define HSTAGE_B 16384
#define GEMMH_SMEM (3 * HSTAGE_B)

__global__ __launch_bounds__(256, 2) void gemm_hf(
    const __half* __restrict__ A, const __half* __restrict__ B,
    float* __restrict__ C, int M, int N, int K) {
    extern __shared__ __align__(16) char gsm[];
    const uint32_t smb = smem_u32(gsm);
    const int tid = threadIdx.x;
    const int wid = tid >> 5;
    const int lane = tid & 31;
    const int bm = blockIdx.y * 128;
    const int bn = blockIdx.x * 128;
    const int wm = (wid >> 1) * 32;
    const int wn = (wid & 1) * 64;
    const int nch = K / 32;

    float acc[2][8][4];
#pragma unroll
    for (int f = 0; f < 2; f++)
#pragma unroll
        for (int n = 0; n < 8; n++)
#pragma unroll
            for (int i = 0; i < 4; i++) acc[f][n][i] = 0.f;

    auto issue = [&](int c, int s) {
        const uint32_t base = smb + (uint32_t)s * HSTAGE_B;
#pragma unroll
        for (int j = 0; j < 2; j++) {
            int ch = tid + 256 * j;
            int r = ch >> 2, sg = ch & 3;
            uint32_t d = swz64((uint32_t)r * 64 + sg * 16);
            cp16(base + d, A + (size_t)(bm + r) * K + c * 32 + sg * 8);
            cp16(base + 8192 + d, B + (size_t)(bn + r) * K + c * 32 + sg * 8);
        }
        CP_COMMIT();
    };

    issue(0, 0);
    if (nch > 1) issue(1, 1);

    const int a_row = lane & 15;
    const int a_k8 = (lane >> 4) << 3;
    const int b_row = (lane & 7) + ((lane & 16) ? 8 : 0);
    const int b_k8 = (lane & 8) ? 8 : 0;

    int st = 0;
    for (int c = 0; c < nch; c++) {
        if (c + 2 < nch) { CP_WAIT(1); } else { CP_WAIT(0); }
        __syncthreads();
        if (c + 2 < nch) {
            int ns = st + 2;
            if (ns >= 3) ns -= 3;
            issue(c + 2, ns);
        }

        const uint32_t kb = smb + (uint32_t)st * HSTAGE_B;
#pragma unroll
        for (int ks = 0; ks < 32; ks += 16) {
            uint32_t af[2][4];
#pragma unroll
            for (int f = 0; f < 2; f++) {
                uint32_t off = swz64((uint32_t)(wm + f * 16 + a_row) * 64 +
                                     (uint32_t)(ks + a_k8) * 2);
                ldm4(af[f], kb + off);
            }
#pragma unroll
            for (int g = 0; g < 4; g++) {
                uint32_t off = swz64((uint32_t)(wn + g * 16 + b_row) * 64 +
                                     (uint32_t)(ks + b_k8) * 2);
                uint32_t t[4];
                ldm4(t, kb + 8192 + off);
                uint32_t b0[2] = {t[0], t[1]}, b1[2] = {t[2], t[3]};
#pragma unroll
                for (int f = 0; f < 2; f++) {
                    mma16816h(acc[f][2 * g], af[f], b0);
                    mma16816h(acc[f][2 * g + 1], af[f], b1);
                }
            }
        }
        if (++st == 3) st = 0;
    }

    const int erow = lane >> 2;
    const int ecol = (lane & 3) * 2;
#pragma unroll
    for (int f = 0; f < 2; f++) {
        const size_t r0 = (size_t)(bm + wm + f * 16 + erow);
#pragma unroll
        for (int n = 0; n < 8; n++) {
            const size_t cc = (size_t)(bn + wn + n * 8 + ecol);
            *(float2*)&C[r0 * N + cc] = make_float2(acc[f][n][0], acc[f][n][1]);
            *(float2*)&C[(r0 + 8) * N + cc] = make_float2(acc[f][n][2], acc[f][n][3]);
        }
    }
}

// ===========================================================================
// RoPE table. sincos(x, SIN, COS) — sin first!
// ===========================================================================
__global__ void rope_table_kernel(float2* __restrict__ t) {
    int i = blockIdx.x * blockDim.x + threadIdx.x;
    int p = i & 31;
    int s = i >> 5;
    double inv = exp(-(double)p * (log(10000.0) / 32.0));
    double a = (double)s * inv;
    double sd, cd;
    sincos(a, &sd, &cd);
    t[i] = make_float2((float)cd, (float)sd);
}

// ===========================================================================
// Prep: RoPE -> fp16 q (pre-scaled 1/32) and k.
// ===========================================================================
__global__ __launch_bounds__(256) void prep_ropeh(
    const float* __restrict__ qp, const float* __restrict__ kp,
    const float2* __restrict__ rope_t,
    __half* __restrict__ qf, __half* __restrict__ kf) {
    size_t i = (size_t)blockIdx.x * 256 + threadIdx.x;   // < BSROWS*512
    int j = (int)(i & 511);
    size_t row = i >> 9;
    int pos = (int)(row & (S_ - 1));
    int pairp = j & 31;
    size_t off = row * DE + 2 * j;
    float2 cs = rope_t[pos * 32 + pairp];

    float2 x = *(const float2*)&qp[off];
    *(uint32_t*)&qf[off] = pk_h2((x.x * cs.x - x.y * cs.y) * 0.03125f,
                                 (x.x * cs.y + x.y * cs.x) * 0.03125f);
    x = *(const float2*)&kp[off];
    *(uint32_t*)&kf[off] = pk_h2(x.x * cs.x - x.y * cs.y,
                                 x.x * cs.y + x.y * cs.x);
}

// ===========================================================================
// Prep: V -> transposed fp16  vt[b][h][d][s]
// ===========================================================================
__global__ __launch_bounds__(256) void prep_vth(const float* __restrict__ vp,
                                                __half* __restrict__ vt) {
    __shared__ float sm[64][65];
    const int tid = threadIdx.x;
    const int st = blockIdx.x, h = blockIdx.y, b = blockIdx.z;

    for (int i = tid; i < 1024; i += 256) {
        int r = i >> 4;
        int f4 = (i & 15) * 4;
        float4 v = *(const float4*)&vp[(size_t)(b * S_ + st * 64 + r) * DE + h * DH + f4];
        sm[r][f4] = v.x; sm[r][f4 + 1] = v.y; sm[r][f4 + 2] = v.z; sm[r][f4 + 3] = v.w;
    }
    __syncthreads();

    const int d = tid >> 2;
    const int ks = (tid & 3) * 16;
    uint32_t pk[8];
#pragma unroll
    for (int j = 0; j < 8; j++)
        pk[j] = pk_h2(sm[ks + 2 * j][d], sm[ks + 2 * j + 1][d]);

    __half* dh = vt + ((size_t)((b * NH + h) * DH + d)) * S_ + st * 64 + ks;
    *(uint4*)&dh[0] = make_uint4(pk[0], pk[1], pk[2], pk[3]);
    *(uint4*)&dh[8] = make_uint4(pk[4], pk[5], pk[6], pk[7]);
}

// ===========================================================================
// fp16 tensor-core causal flash attention, cp.async 3-stage ring.
// Block = 128 q rows of one (b,h), 8 warps x 16 rows; 64-key tiles.
// Epilogue writes fp16 directly into the O-GEMM A-staging buffer.
// Stage layout: K rows 0-63 at [r*AP], V(d) rows 0-63 at [(64+r)*AP].
// ===========================================================================
#define AP 72
#define STGE (128 * AP)                // halves per stage
#define ATTN_SMEM (3 * STGE * 2)       // 55,296 B

__global__ __launch_bounds__(256) void attn_hf(
    const __half* __restrict__ qf, const __half* __restrict__ kf,
    const __half* __restrict__ vt, __half* __restrict__ af) {
    extern __shared__ __align__(16) __half sm[];

    const int tid = threadIdx.x;
    const int w = tid >> 5;
    const int lane = tid & 31;
    const int b = blockIdx.z, h = blockIdx.y;
    const int q0 = blockIdx.x * 128;
    const uint32_t smb = smem_u32(sm);
    const int nkt = 2 * blockIdx.x + 2;

    const __half* Kf = kf + (size_t)b * S_ * DE + h * DH;
    const __half* Vt = vt + (size_t)(b * NH + h) * DH * S_;

    const int cr = tid >> 3;        // 0..31
    const int csg = tid & 7;

    auto issue = [&](int k0, int s) {
        const uint32_t base = smb + (uint32_t)s * STGE * 2;
#pragma unroll
        for (int j = 0; j < 2; j++) {
            int r = cr + 32 * j;
            uint32_t dof = ((uint32_t)r * AP + csg * 8) * 2;
            cp16(base + dof, Kf + (size_t)(k0 + r) * DE + csg * 8);
            cp16(base + 64 * AP * 2 + dof, Vt + (size_t)r * S_ + k0 + csg * 8);
        }
        CP_COMMIT();
    };

    issue(0, 0);
    if (nkt > 1) issue(64, 1);

    // stage Q into stage-2 buffer (free until tile 2), extract fragments
    {
        __half* qs = sm + 2 * STGE;
        const __half* sh = qf + (size_t)(b * S_ + q0) * DE + h * DH;
#pragma unroll
        for (int j = 0; j < 4; j++) {
            int i = tid + 256 * j;
            int r = i >> 3, sg = i & 7;
            *(uint4*)&qs[r * AP + sg * 8] = *(const uint4*)&sh[(size_t)r * DE + sg * 8];
        }
    }
    __syncthreads();

    uint32_t qfr[4][4];
    {
        const uint32_t qb = smb + 2 * STGE * 2;
        const int arow = w * 16 + (lane & 15);
        const int ak8 = (lane >> 4) << 3;
#pragma unroll
        for (int kc = 0; kc < 4; kc++)
            ldm4(qfr[kc], qb + (uint32_t)(arow * AP + kc * 16 + ak8) * 2);
    }
    __syncthreads();

    float oacc[8][4];
#pragma unroll
    for (int n = 0; n < 8; n++)
#pragma unroll
        for (int i = 0; i < 4; i++) oacc[n][i] = 0.f;
    float m0 = -1e30f, m1 = -1e30f, l0 = 0.f, l1 = 0.f;

    const int row0 = q0 + w * 16 + (lane >> 2);
    const int brow = (lane & 7) + ((lane & 16) ? 8 : 0);
    const int bk8 = (lane & 8) ? 8 : 0;

    int bufsel = 0;
    for (int kt = 0; kt < nkt; kt++) {
        const int k0 = kt * 64;
        if (kt + 2 < nkt) { CP_WAIT(1); } else { CP_WAIT(0); }
        __syncthreads();
        if (kt + 2 < nkt) {
            int nb = bufsel + 2;
            if (nb >= 3) nb -= 3;
            issue(k0 + 128, nb);
        }

        const uint32_t kb = smb + (uint32_t)bufsel * STGE * 2;

        // ---- S = Q K^T ----
        float sacc[8][4];
#pragma unroll
        for (int n = 0; n < 8; n++)
#pragma unroll
            for (int i = 0; i < 4; i++) sacc[n][i] = 0.f;

#pragma unroll
        for (int kc = 0; kc < 4; kc++)
#pragma unroll
            for (int g = 0; g < 4; g++) {
                uint32_t off = (uint32_t)((g * 16 + brow) * AP + kc * 16 + bk8) * 2;
                uint32_t t[4];
                ldm4(t, kb + off);
                uint32_t b0[2] = {t[0], t[1]}, b1[2] = {t[2], t[3]};
                mma16816h(sacc[2 * g], qfr[kc], b0);
                mma16816h(sacc[2 * g + 1], qfr[kc], b1);
            }

        // ---- causal mask ----
        if (kt >= nkt - 2) {
#pragma unroll
            for (int n = 0; n < 8; n++) {
                int col = k0 + n * 8 + (lane & 3) * 2;
                if (col > row0) sacc[n][0] = -1e30f;
                if (col + 1 > row0) sacc[n][1] = -1e30f;
                if (col > row0 + 8) sacc[n][2] = -1e30f;
                if (col + 1 > row0 + 8) sacc[n][3] = -1e30f;
            }
        }

        // ---- online softmax ----
        float mt0 = -1e30f, mt1 = -1e30f;
#pragma unroll
        for (int n = 0; n < 8; n++) {
            mt0 = fmaxf(mt0, fmaxf(sacc[n][0], sacc[n][1]));
            mt1 = fmaxf(mt1, fmaxf(sacc[n][2], sacc[n][3]));
        }
        mt0 = fmaxf(mt0, __shfl_xor_sync(0xffffffffu, mt0, 1));
        mt0 = fmaxf(mt0, __shfl_xor_sync(0xffffffffu, mt0, 2));
        mt1 = fmaxf(mt1, __shfl_xor_sync(0xffffffffu, mt1, 1));
        mt1 = fmaxf(mt1, __shfl_xor_sync(0xffffffffu, mt1, 2));

        float mn0 = fmaxf(m0, mt0), mn1 = fmaxf(m1, mt1);
        float a0 = __expf(m0 - mn0), a1 = __expf(m1 - mn1);
        m0 = mn0; m1 = mn1;

        float s0 = 0.f, s1 = 0.f;
#pragma unroll
        for (int n = 0; n < 8; n++) {
            sacc[n][0] = __expf(sacc[n][0] - mn0);
            sacc[n][1] = __expf(sacc[n][1] - mn0);
            sacc[n][2] = __expf(sacc[n][2] - mn1);
            sacc[n][3] = __expf(sacc[n][3] - mn1);
            s0 += sacc[n][0] + sacc[n][1];
            s1 += sacc[n][2] + sacc[n][3];
        }
        s0 += __shfl_xor_sync(0xffffffffu, s0, 1);
        s0 += __shfl_xor_sync(0xffffffffu, s0, 2);
        s1 += __shfl_xor_sync(0xffffffffu, s1, 1);
        s1 += __shfl_xor_sync(0xffffffffu, s1, 2);
        l0 = l0 * a0 + s0;
        l1 = l1 * a1 + s1;
#pragma unroll
        for (int n = 0; n < 8; n++) {
            oacc[n][0] *= a0; oacc[n][1] *= a0;
            oacc[n][2] *= a1; oacc[n][3] *= a1;
        }

        // ---- O += P V ----
#pragma unroll
        for (int kc = 0; kc < 4; kc++) {
            uint32_t pa[4];
            pa[0] = pk_h2(sacc[2 * kc][0], sacc[2 * kc][1]);
            pa[1] = pk_h2(sacc[2 * kc][2], sacc[2 * kc][3]);
            pa[2] = pk_h2(sacc[2 * kc + 1][0], sacc[2 * kc + 1][1]);
            pa[3] = pk_h2(sacc[2 * kc + 1][2], sacc[2 * kc + 1][3]);
#pragma unroll
            for (int g = 0; g < 4; g++) {
                uint32_t off = (uint32_t)((64 + g * 16 + brow) * AP + kc * 16 + bk8) * 2;
                uint32_t t[4];
                ldm4(t, kb + off);
                uint32_t b0[2] = {t[0], t[1]}, b1[2] = {t[2], t[3]};
                mma16816h(oacc[2 * g], pa, b0);
                mma16816h(oacc[2 * g + 1], pa, b1);
            }
        }

        if (++bufsel == 3) bufsel = 0;
    }

    // ---- epilogue: fp16 directly into O-GEMM A staging ----
    const float inv0 = 1.0f / l0, inv1 = 1.0f / l1;
    const size_t gr0 = (size_t)(b * S_ + row0);
#pragma unroll
    for (int n = 0; n < 8; n++) {
        const size_t cc = (size_t)(h * DH + n * 8 + (lane & 3) * 2);
        *(uint32_t*)&af[gr0 * DE + cc] = pk_h2(oacc[n][0] * inv0, oacc[n][1] * inv0);
        *(uint32_t*)&af[(gr0 + 8) * DE + cc] = pk_h2(oacc[n][2] * inv1, oacc[n][3] * inv1);
    }
}

// ===========================================================================
extern "C" void kernel_launch(void* const* d_in, const int* in_sizes, int n_in,
                              void* d_out, int out_size) {
    const float* q  = (const float*)d_in[0];
    const float* k  = (const float*)d_in[1];
    const float* v  = (const float*)d_in[2];
    const float* Wq = (const float*)d_in[3];
    const float* Wk = (const float*)d_in[4];
    const float* Wv = (const float*)d_in[5];
    const float* Wo = (const float*)d_in[6];
    float* out = (float*)d_out;

    float *qp, *kp, *vp;
    float2* rope_t;
    __half *qf, *kf, *vt, *af, *wf;
    cudaGetSymbolAddress((void**)&qp, g_qp);
    cudaGetSymbolAddress((void**)&kp, g_kp);
    cudaGetSymbolAddress((void**)&vp, g_vp);
    cudaGetSymbolAddress((void**)&rope_t, g_rope);
    cudaGetSymbolAddress((void**)&qf, g_qf2);
    cudaGetSymbolAddress((void**)&kf, g_kf2);
    cudaGetSymbolAddress((void**)&vt, g_vt2);
    cudaGetSymbolAddress((void**)&af, g_af);
    cudaGetSymbolAddress((void**)&wf, g_wf);

    cudaFuncSetAttribute(attn_hf, cudaFuncAttributeMaxDynamicSharedMemorySize,
                         ATTN_SMEM);
    cudaFuncSetAttribute(gemm_hf, cudaFuncAttributeMaxDynamicSharedMemorySize,
                         GEMMH_SMEM);

    rope_table_kernel<<<(S_ * 32) / 256, 256>>>(rope_t);

    const int n_qk = BSROWS * 2 * DE;
    const int n_v  = BSROWS * DE;
    const int n_w2 = DE * 2 * DE;
    const int n_w1 = DE * DE;
    dim3 gq(DE / 128, BSROWS / 128);       // (8, 64)

    // Q projection
    prep_h<<<n_w2 / 1024, 256>>>(Wq, wf, n_w2 / 4);
    prep_h<<<n_qk / 1024, 256>>>(q, af, n_qk / 4);
    gemm_hf<<<gq, 256, GEMMH_SMEM>>>(af, wf, qp, BSROWS, DE, 2 * DE);
    // K projection
    prep_h<<<n_w2 / 1024, 256>>>(Wk, wf, n_w2 / 4);
    prep_h<<<n_qk / 1024, 256>>>(k, af, n_qk / 4);
    gemm_hf<<<gq, 256, GEMMH_SMEM>>>(af, wf, kp, BSROWS, DE, 2 * DE);
    // V projection
    prep_h<<<n_w1 / 1024, 256>>>(Wv, wf, n_w1 / 4);
    prep_h<<<n_v / 1024, 256>>>(v, af, n_v / 4);
    gemm_hf<<<gq, 256, GEMMH_SMEM>>>(af, wf, vp, BSROWS, DE, DE);

    prep_ropeh<<<(BSROWS * 512) / 256, 256>>>(qp, kp, rope_t, qf, kf);
    prep_vth<<<dim3(S_ / 64, NH, B_), 256>>>(vp, vt);

    // attention writes fp16 directly into af (O-GEMM A operand)
    attn_hf<<<dim3(S_ / 128, NH, B_), 256, ATTN_SMEM>>>(qf, kf, vt, af);

    // Output projection
    prep_h<<<n_w1 / 1024, 256>>>(Wo, wf, n_w1 / 4);
    gemm_hf<<<gq, 256, GEMMH_SMEM>>>(af, wf, out, BSROWS, DE, DE);
}